// round 9
// baseline (speedup 1.0000x reference)
#include <cuda_runtime.h>
#include <cuda_bf16.h>
#include <cstdint>
#include <math.h>

#define NBATCH 4
#define CH     256
#define NPIX   4096
#define KD     32
#define NZ     8   // 2 branches x 4 batches

// ---- scratch (module-load allocated; no runtime alloc) ----
__device__ __nv_bfloat16 g_fT[NZ][NPIX][KD];         // f^T : [n][k] bf16
__device__ __nv_bfloat16 g_gT[NZ][NPIX][KD];         // g^T : [m][k] bf16
__device__ float         g_invsum[NZ][NPIX];         // 1 / softmax row sum (shifted)
__device__ __nv_bfloat16 g_Xt[NZ][NPIX][CH];         // x^T : [n][c] bf16
__device__ __nv_bfloat16 g_Hb[NZ][CH][NPIX];         // h projection (invsum-scaled), bf16
__device__ __nv_bfloat16 g_Pt[NZ][NPIX][NPIX];       // unnormalized P^T bf16: Pt[m][n]

__device__ __forceinline__ uint32_t smem_u32(const void* p) {
    uint32_t a;
    asm("{ .reg .u64 t; cvta.to.shared.u64 t, %1; cvt.u32.u64 %0, t; }" : "=r"(a) : "l"(p));
    return a;
}

__device__ __forceinline__ float ex2f(float x) {
    float r;
    asm("ex2.approx.f32 %0, %1;" : "=f"(r) : "f"(x));
    return r;
}

#define CP_ASYNC16(dst, src) \
    asm volatile("cp.async.cg.shared.global [%0], [%1], 16;" :: "r"(dst), "l"(src))
#define CP_ASYNC_COMMIT() asm volatile("cp.async.commit_group;" ::: "memory")
#define CP_ASYNC_WAIT_1() asm volatile("cp.async.wait_group 1;" ::: "memory")
#define CP_ASYNC_WAIT_0() asm volatile("cp.async.wait_group 0;" ::: "memory")

#define LDSM_X4(r0,r1,r2,r3,addr) \
    asm volatile("ldmatrix.sync.aligned.m8n8.x4.shared.b16 {%0,%1,%2,%3}, [%4];" \
        : "=r"(r0), "=r"(r1), "=r"(r2), "=r"(r3) : "r"(addr))

#define MMA_BF16(c0,c1,c2,c3,a0,a1,a2,a3,b0,b1) \
    asm volatile("mma.sync.aligned.m16n8k16.row.col.f32.bf16.bf16.f32 " \
        "{%0,%1,%2,%3}, {%4,%5,%6,%7}, {%8,%9}, {%0,%1,%2,%3};" \
        : "+f"(c0), "+f"(c1), "+f"(c2), "+f"(c3) \
        : "r"(a0), "r"(a1), "r"(a2), "r"(a3), "r"(b0), "r"(b1))

// =====================================================================
// SIMT SGEMM body (fp32) — used only for the small f/g projection.
// C is bf16 [Nglobal][KD], stores C[n][k] = acc^T.
// =====================================================================
template<int BM, int BN, int BK2, int TM, int TN>
__device__ __forceinline__ void sgemm_trans_body(
    const float* __restrict__ A, const float* __restrict__ B,
    __nv_bfloat16* __restrict__ C,
    int K, int ldA, int ldB,
    int tileCol,
    const float* __restrict__ bias)
{
    constexpr int THREADS = (BM/TM)*(BN/TN);
    __shared__ float As[BK2][BM];
    __shared__ float Bs[BK2][BN];
    const int tid = threadIdx.x;
    const int tx = tid % (BN/TN);
    const int ty = tid / (BN/TN);

    B += (size_t)tileCol * BN;

    constexpr int AVR = BK2/4;
    const int aRow = tid / AVR;
    const int aCol = (tid % AVR)*4;
    constexpr int ARS = THREADS / AVR;
    constexpr int AIT = BM / ARS;

    constexpr int BVR = BN/4;
    const int bRow = tid / BVR;
    const int bCol = (tid % BVR)*4;
    constexpr int BRS = THREADS / BVR;
    constexpr int BIT = BK2 / BRS;

    float4 aF[AIT], bF[BIT];
#pragma unroll
    for (int i=0;i<AIT;i++)
        aF[i] = *reinterpret_cast<const float4*>(&A[(size_t)(aRow+i*ARS)*ldA + aCol]);
#pragma unroll
    for (int i=0;i<BIT;i++)
        bF[i] = *reinterpret_cast<const float4*>(&B[(size_t)(bRow+i*BRS)*ldB + bCol]);

    float acc[TM][TN];
#pragma unroll
    for (int i=0;i<TM;i++)
#pragma unroll
        for (int j=0;j<TN;j++) acc[i][j] = 0.f;

    for (int kb = 0; kb < K; kb += BK2) {
        __syncthreads();
#pragma unroll
        for (int i=0;i<AIT;i++){
            As[aCol+0][aRow+i*ARS] = aF[i].x;
            As[aCol+1][aRow+i*ARS] = aF[i].y;
            As[aCol+2][aRow+i*ARS] = aF[i].z;
            As[aCol+3][aRow+i*ARS] = aF[i].w;
        }
#pragma unroll
        for (int i=0;i<BIT;i++)
            *reinterpret_cast<float4*>(&Bs[bRow+i*BRS][bCol]) = bF[i];
        __syncthreads();

        if (kb + BK2 < K) {
#pragma unroll
            for (int i=0;i<AIT;i++)
                aF[i] = *reinterpret_cast<const float4*>(
                    &A[(size_t)(aRow+i*ARS)*ldA + (kb+BK2) + aCol]);
#pragma unroll
            for (int i=0;i<BIT;i++)
                bF[i] = *reinterpret_cast<const float4*>(
                    &B[(size_t)(kb+BK2+bRow+i*BRS)*ldB + bCol]);
        }

#pragma unroll
        for (int k=0;k<BK2;k++){
            float ra[TM], rb[TN];
#pragma unroll
            for (int i=0;i<TM;i+=4){
                float4 v = *reinterpret_cast<const float4*>(&As[k][ty*TM+i]);
                ra[i]=v.x; ra[i+1]=v.y; ra[i+2]=v.z; ra[i+3]=v.w;
            }
#pragma unroll
            for (int j=0;j<TN;j+=4){
                float4 v = *reinterpret_cast<const float4*>(&Bs[k][tx*TN+j]);
                rb[j]=v.x; rb[j+1]=v.y; rb[j+2]=v.z; rb[j+3]=v.w;
            }
#pragma unroll
            for (int i=0;i<TM;i++)
#pragma unroll
                for (int j=0;j<TN;j++)
                    acc[i][j] = fmaf(ra[i], rb[j], acc[i][j]);
        }
    }

#pragma unroll
    for (int i=0;i<TM;i++){
        const int row = ty*TM + i;                 // k index
        const float bv = bias ? bias[row] : 0.f;
#pragma unroll
        for (int j=0;j<TN;j++){
            const int col = tileCol*BN + tx*TN + j;  // n index
            C[(size_t)col * KD + row] = __float2bfloat16(acc[i][j] + bv);
        }
    }
}

// =====================================================================
// Kernel 0: transpose x (fp32 [c][n]) -> Xt bf16 [n][c]
// =====================================================================
__global__ __launch_bounds__(256) void xt_kernel(
    const float* __restrict__ x1, const float* __restrict__ x2)
{
    const int z  = blockIdx.z;
    const int br = z >> 2, b = z & 3;
    const float* X = (br ? x2 : x1) + (size_t)b * CH * NPIX;
    const int n0 = blockIdx.x * 64;
    const int c0 = blockIdx.y * 64;

    __shared__ unsigned short t[64][66];
    const int tid = threadIdx.x;
    const int rr = tid >> 4;
    const int c4 = (tid & 15) * 4;

#pragma unroll
    for (int p=0;p<4;p++){
        const int crow = rr + p*16;
        const float4 v = *reinterpret_cast<const float4*>(
            &X[(size_t)(c0 + crow) * NPIX + n0 + c4]);
        t[crow][c4+0] = __bfloat16_as_ushort(__float2bfloat16(v.x));
        t[crow][c4+1] = __bfloat16_as_ushort(__float2bfloat16(v.y));
        t[crow][c4+2] = __bfloat16_as_ushort(__float2bfloat16(v.z));
        t[crow][c4+3] = __bfloat16_as_ushort(__float2bfloat16(v.w));
    }
    __syncthreads();

#pragma unroll
    for (int p=0;p<4;p++){
        const int nrow = rr + p*16;
        uint2 u;
        u.x = (uint32_t)t[c4+0][nrow] | ((uint32_t)t[c4+1][nrow] << 16);
        u.y = (uint32_t)t[c4+2][nrow] | ((uint32_t)t[c4+3][nrow] << 16);
        *reinterpret_cast<uint2*>(&g_Xt[z][n0 + nrow][c0 + c4]) = u;
    }
}

// =====================================================================
// Kernel 1: f/g projections -> transposed bf16 [n][32]
// =====================================================================
__global__ __launch_bounds__(256) void proj_fg_kernel(
    const float* __restrict__ x1, const float* __restrict__ x2,
    const float* __restrict__ f_w, const float* __restrict__ f_b,
    const float* __restrict__ g_w, const float* __restrict__ g_b)
{
    const int z  = blockIdx.z;
    const int br = z >> 2, b = z & 3;
    const int fg = blockIdx.y;
    const float* W    = fg ? g_w : f_w;
    const float* bias = fg ? g_b : f_b;
    const float* X    = (br ? x2 : x1) + (size_t)b * CH * NPIX;
    __nv_bfloat16* C = fg ? &g_gT[z][0][0] : &g_fT[z][0][0];
    sgemm_trans_body<32,128,32,4,4>(W, X, C, CH, CH, NPIX, blockIdx.x, bias);
}

// =====================================================================
// Kernel 2 (fused, single pass): scores (HMMA bf16) + fixed-shift exp +
// transposed bf16 P' write + shifted row sums.  (unchanged)
// =====================================================================
#define FLD   40
#define FSM_FT   0u
#define FSM_G    5120u
#define FSM_GSZ  20480u
#define FSM_ST   46080u
#define FSM_RED  82944u
#define FSM_TOTAL 83968u

__global__ __launch_bounds__(256) void fused_sm_kernel()
{
    extern __shared__ __align__(16) char sm[];
    const uint32_t smBase = smem_u32(sm);
    float* red = reinterpret_cast<float*>(sm + FSM_RED);

    const int tid  = threadIdx.x;
    const int lane = tid & 31, wid = tid >> 5;
    const int z  = blockIdx.y;
    const int n0 = blockIdx.x * 64;
    const int warpM = wid >> 2;
    const int warpN = wid & 3;
    const int qg = lane >> 2, tq = lane & 3;

    {
        const int row = tid >> 2, ch = tid & 3;
        CP_ASYNC16(smBase + FSM_FT + (uint32_t)((row*FLD + ch*8)*2),
                   (const char*)&g_fT[z][n0 + row][ch*8]);
    }
    CP_ASYNC_COMMIT();

    const int lm  = lane & 15;
    const int aco = (lane >= 16) ? 8 : 0;
    uint32_t aAddr[2];
#pragma unroll
    for (int mt=0; mt<2; mt++)
        aAddr[mt] = smBase + FSM_FT +
            (uint32_t)(((warpM*32 + mt*16 + lm)*FLD + aco)*2);
    const int bro = (lane & 7) + ((lane >= 16) ? 8 : 0);
    const int bco = (lane & 8) ? 8 : 0;
    uint32_t bOff[4];
#pragma unroll
    for (int p=0; p<4; p++)
        bOff[p] = (uint32_t)(((warpN*64 + p*16 + bro)*FLD + bco)*2);

    const int grow = tid >> 2, gch = tid & 3;

    float rsum[4];
#pragma unroll
    for (int i=0;i<4;i++) rsum[i] = 0.f;

    const float CEXP  = 0.17677669529663688f * 1.4426950408889634f;
    const float SHIFT = 16.0f * 1.4426950408889634f;

    {
        const char* src = (const char*)&g_gT[z][0][0];
#pragma unroll
        for (int i=0;i<4;i++)
            CP_ASYNC16(smBase + FSM_G + (uint32_t)(((grow+i*64)*FLD + gch*8)*2),
                       src + (size_t)(grow + i*64)*64 + gch*16);
        CP_ASYNC_COMMIT();
    }
    for (int t = 0; t < 16; ++t) {
        if (t < 15) {
            const uint32_t dst = smBase + FSM_G + (uint32_t)((t+1)&1)*FSM_GSZ;
            const char* src = (const char*)&g_gT[z][(t+1)*256][0];
#pragma unroll
            for (int i=0;i<4;i++)
                CP_ASYNC16(dst + (uint32_t)(((grow+i*64)*FLD + gch*8)*2),
                           src + (size_t)(grow + i*64)*64 + gch*16);
            CP_ASYNC_COMMIT();
            CP_ASYNC_WAIT_1();
        } else {
            CP_ASYNC_WAIT_0();
        }
        __syncthreads();

        const uint32_t gb = smBase + FSM_G + (uint32_t)(t&1)*FSM_GSZ;
        float acc[2][8][4];
#pragma unroll
        for (int mt=0;mt<2;mt++)
#pragma unroll
            for (int nt=0;nt<8;nt++)
#pragma unroll
                for (int c=0;c<4;c++) acc[mt][nt][c] = 0.f;

#pragma unroll
        for (int ks = 0; ks < 2; ++ks) {
            uint32_t a[2][4];
#pragma unroll
            for (int mt=0; mt<2; mt++)
                LDSM_X4(a[mt][0], a[mt][1], a[mt][2], a[mt][3],
                        aAddr[mt] + ks*32);
            uint32_t bb[4][4];
#pragma unroll
            for (int p=0; p<4; p++)
                LDSM_X4(bb[p][0], bb[p][1], bb[p][2], bb[p][3],
                        gb + bOff[p] + ks*32);
#pragma unroll
            for (int mt=0; mt<2; mt++)
#pragma unroll
                for (int nt=0; nt<8; nt++) {
                    const uint32_t b0 = bb[nt>>1][(nt&1)*2];
                    const uint32_t b1 = bb[nt>>1][(nt&1)*2+1];
                    MMA_BF16(acc[mt][nt][0], acc[mt][nt][1],
                             acc[mt][nt][2], acc[mt][nt][3],
                             a[mt][0], a[mt][1], a[mt][2], a[mt][3], b0, b1);
                }
        }

        {
            __nv_bfloat16* stg = reinterpret_cast<__nv_bfloat16*>(sm + FSM_ST);
#pragma unroll
            for (int mt=0;mt<2;mt++)
#pragma unroll
                for (int nt=0;nt<8;nt++)
#pragma unroll
                    for (int c=0;c<4;c++){
                        const int idx = mt*2 + (c>>1);
                        const float p = ex2f(fmaf(acc[mt][nt][c], CEXP, -SHIFT));
                        rsum[idx] += p;
                        const int ml = warpN*64 + nt*8 + tq*2 + (c&1);
                        const int nl = warpM*32 + mt*16 + qg + (c>>1)*8;
                        stg[ml*72 + nl] = __float2bfloat16(p);
                    }
            __syncthreads();
            const int ch = tid & 7;
#pragma unroll
            for (int i=0;i<8;i++){
                const int ml = (tid>>3) + i*32;
                const uint4 v = *reinterpret_cast<const uint4*>(
                    sm + FSM_ST + (uint32_t)((ml*72 + ch*8)*2));
                *reinterpret_cast<uint4*>(&g_Pt[z][t*256 + ml][n0 + ch*8]) = v;
            }
            __syncthreads();
        }
    }

#pragma unroll
    for (int i=0;i<4;i++){
        float v = rsum[i];
        v += __shfl_xor_sync(0xffffffffu, v, 1);
        v += __shfl_xor_sync(0xffffffffu, v, 2);
        rsum[i] = v;
    }
    if (tq == 0) {
#pragma unroll
        for (int i=0;i<4;i++){
            const int r = warpM*32 + (i>>1)*16 + qg + (i&1)*8;
            red[r*4 + warpN] = rsum[i];
        }
    }
    __syncthreads();
    if (warpN == 0 && tq == 0) {
#pragma unroll
        for (int i=0;i<4;i++){
            const int r = warpM*32 + (i>>1)*16 + qg + (i&1)*8;
            const float s = red[r*4+0] + red[r*4+1] + red[r*4+2] + red[r*4+3];
            g_invsum[z][n0 + r] = 1.0f / s;
        }
    }
}

// =====================================================================
// Kernel 3: h projection via HMMA.  CTA 64(o) x 128(n), 128 threads,
// 4 warps of 64x32, K=256 single shot.  2 CTAs/SM.
// grid (32 n-tiles, 4 o-tiles, NZ) = 1024 CTAs.
// =====================================================================
#define PH_LDA  264                          // padded k stride (elems)
#define PH_B    (64*PH_LDA*2)                // A region: 33792; B starts after
#define PH_SMEM ((64+128)*PH_LDA*2)          // 101376

__global__ void __launch_bounds__(128, 2) proj_h_mma_kernel(
    const float* __restrict__ h1w, const float* __restrict__ h1b,
    const float* __restrict__ h2w, const float* __restrict__ h2b)
{
    extern __shared__ char smh[];
    const uint32_t smBase = smem_u32(smh);

    const int tid = threadIdx.x;
    const int wid = tid >> 5, lane = tid & 31;
    const int z = blockIdx.z, br = z >> 2;
    const int nBase = blockIdx.x * 128;
    const int oBase = blockIdx.y * 64;
    const float* W    = br ? h2w : h1w;
    const float* bias = br ? h2b : h1b;

    // ---- load B: Xt[nBase+r][0..256) bf16 via cp.async (1 thread/row) ----
    {
        const char* src = (const char*)&g_Xt[z][nBase + tid][0];
        const uint32_t dst = smBase + PH_B + (uint32_t)(tid * (PH_LDA*2));
#pragma unroll
        for (int j=0;j<32;j++) CP_ASYNC16(dst + j*16, src + j*16);
        CP_ASYNC_COMMIT();
    }
    // ---- load A: W[oBase+r][0..256) fp32 -> bf16 smem ----
    {
        const int r = tid >> 1;
        const int half = (tid & 1) * 128;
        const float* src = W + (size_t)(oBase + r) * CH + half;
        char* dst = smh + (size_t)((r*PH_LDA + half)*2);
#pragma unroll
        for (int j=0;j<32;j++){
            const float4 v = *reinterpret_cast<const float4*>(src + j*4);
            __nv_bfloat162 p0 = __float22bfloat162_rn(make_float2(v.x, v.y));
            __nv_bfloat162 p1 = __float22bfloat162_rn(make_float2(v.z, v.w));
            uint2 u;
            u.x = reinterpret_cast<uint32_t&>(p0);
            u.y = reinterpret_cast<uint32_t&>(p1);
            *reinterpret_cast<uint2*>(dst + j*8) = u;
        }
    }
    CP_ASYNC_WAIT_0();
    __syncthreads();

    // ---- ldmatrix lane offsets: warp = 64(o) x 32(n) at warpN = wid ----
    const int warpN = wid;               // 0..3
    const int lm  = lane & 15;
    const int aco = (lane >= 16) ? 8 : 0;
    uint32_t aAddr[4];
#pragma unroll
    for (int mt=0; mt<4; mt++)
        aAddr[mt] = smBase + (uint32_t)(((mt*16 + lm)*PH_LDA + aco)*2);
    const int bro = (lane & 7) + ((lane >= 16) ? 8 : 0);
    const int bco = (lane & 8) ? 8 : 0;
    uint32_t bAddr[2];
#pragma unroll
    for (int p=0; p<2; p++)
        bAddr[p] = smBase + PH_B + (uint32_t)(((warpN*32 + p*16 + bro)*PH_LDA + bco)*2);

    float acc[4][4][4];
#pragma unroll
    for (int i=0;i<4;i++)
#pragma unroll
        for (int j=0;j<4;j++)
#pragma unroll
            for (int k=0;k<4;k++) acc[i][j][k] = 0.f;

#pragma unroll
    for (int ks = 0; ks < 16; ++ks) {
        uint32_t a[4][4];
#pragma unroll
        for (int mt=0; mt<4; mt++)
            LDSM_X4(a[mt][0], a[mt][1], a[mt][2], a[mt][3],
                    aAddr[mt] + ks*32);
        uint32_t bb[2][4];
#pragma unroll
        for (int p=0; p<2; p++)
            LDSM_X4(bb[p][0], bb[p][1], bb[p][2], bb[p][3],
                    bAddr[p] + ks*32);
#pragma unroll
        for (int mt=0; mt<4; mt++)
#pragma unroll
            for (int nt=0; nt<4; nt++) {
                const uint32_t b0 = bb[nt>>1][(nt&1)*2];
                const uint32_t b1 = bb[nt>>1][(nt&1)*2+1];
                MMA_BF16(acc[mt][nt][0], acc[mt][nt][1],
                         acc[mt][nt][2], acc[mt][nt][3],
                         a[mt][0], a[mt][1], a[mt][2], a[mt][3], b0, b1);
            }
    }

    // ---- epilogue: H' = (acc + bias[o]) * invsum[n] -> bf16 ----
    const int g  = lane >> 2;
    const int tq = lane & 3;
#pragma unroll
    for (int mt=0; mt<4; mt++) {
        const int row0 = oBase + mt*16 + g;
        const float bv0 = bias[row0];
        const float bv8 = bias[row0 + 8];
#pragma unroll
        for (int nt=0; nt<4; nt++) {
            const int col = nBase + warpN*32 + nt*8 + tq*2;
            const float2 iv = *reinterpret_cast<const float2*>(&g_invsum[z][col]);
            {
                const float v0 = (acc[mt][nt][0] + bv0) * iv.x;
                const float v1 = (acc[mt][nt][1] + bv0) * iv.y;
                __nv_bfloat162 pk = __float22bfloat162_rn(make_float2(v0, v1));
                *reinterpret_cast<uint32_t*>(&g_Hb[z][row0][col]) =
                    reinterpret_cast<uint32_t&>(pk);
            }
            {
                const float v0 = (acc[mt][nt][2] + bv8) * iv.x;
                const float v1 = (acc[mt][nt][3] + bv8) * iv.y;
                __nv_bfloat162 pk = __float22bfloat162_rn(make_float2(v0, v1));
                *reinterpret_cast<uint32_t*>(&g_Hb[z][row0 + 8][col]) =
                    reinterpret_cast<uint32_t&>(pk);
            }
        }
    }
}

// =====================================================================
// Kernel 4: out[z] = gamma * (H' @ P') + x  via mma.sync bf16 (HMMA).
// Round-5 config + per-warp ks-stagger (de-phase LDSM vs MMA across
// warps) + prefetch issued after first ks block.
// =====================================================================
#define BK      64
#define LDSS    72
#define STGB    (128*LDSS*2)             // 18432 bytes per operand per stage
#define NSTG    3
#define OUT_SMEM (NSTG*2*STGB)           // 110592

__global__ void __launch_bounds__(256, 2) out_mma_kernel(
    const float* __restrict__ x1, const float* __restrict__ x2,
    const float* __restrict__ gamma1, const float* __restrict__ gamma2,
    float* __restrict__ out)
{
    extern __shared__ char smo[];
    const uint32_t smBase = smem_u32(smo);

    const int tid = threadIdx.x;
    const int wid = tid >> 5, lane = tid & 31;
    const int z = blockIdx.z, br = z >> 2, b = z & 3;
    const int mBase = blockIdx.x * 128;
    const int cBase = blockIdx.y * 128;
    const float* X = (br ? x2 : x1) + (size_t)b * CH * NPIX;
    const float gamma = (br ? gamma2 : gamma1)[0];

    const int lrow = tid >> 1;
    const int lcol = (tid & 1) * 32;
    const char* gAp = (const char*)(&g_Hb[z][cBase + lrow][lcol]);
    const char* gBp = (const char*)(&g_Pt[z][mBase + lrow][lcol]);
    const uint32_t ldOff = (uint32_t)((lrow*LDSS + lcol)*2);

    const int warpM = wid >> 2;
    const int warpN = wid & 3;
    const int lm  = lane & 15;
    const int aco = (lane >= 16) ? 8 : 0;
    uint32_t aOff[4];
#pragma unroll
    for (int mt=0; mt<4; mt++)
        aOff[mt] = (uint32_t)(((warpM*64 + mt*16 + lm)*LDSS + aco)*2);
    const int bro = (lane & 7) + ((lane >= 16) ? 8 : 0);
    const int bco = (lane & 8) ? 8 : 0;
    uint32_t bOff[2];
#pragma unroll
    for (int p=0; p<2; p++)
        bOff[p] = (uint32_t)(((warpN*32 + p*16 + bro)*LDSS + bco)*2) + STGB;

    const int ko = wid & 3;   // per-warp ks stagger

    float acc[4][4][4];
#pragma unroll
    for (int i=0;i<4;i++)
#pragma unroll
        for (int j=0;j<4;j++)
#pragma unroll
            for (int k=0;k<4;k++) acc[i][j][k] = 0.f;

#pragma unroll
    for (int st=0; st<2; ++st) {
        const uint32_t slot = smBase + (uint32_t)st * (2*STGB);
        const char* sa = gAp + (size_t)st * (BK*2);
        const char* sb = gBp + (size_t)st * (BK*2);
#pragma unroll
        for (int j=0;j<4;j++) CP_ASYNC16(slot + ldOff + j*16, sa + j*16);
#pragma unroll
        for (int j=0;j<4;j++) CP_ASYNC16(slot + STGB + ldOff + j*16, sb + j*16);
        CP_ASYNC_COMMIT();
    }

    int slotC = 0;
    int slotP = 2;
    for (int it = 0; it < NPIX/BK; ++it) {
        CP_ASYNC_WAIT_1();
        __syncthreads();

        const uint32_t sbk = smBase + (uint32_t)slotC * (2*STGB);

        // ---- first ks block (ks = ko) ----
        {
            const int ks = ko;
            uint32_t a[4][4];
#pragma unroll
            for (int mt=0; mt<4; mt++)
                LDSM_X4(a[mt][0], a[mt][1], a[mt][2], a[mt][3],
                        sbk + aOff[mt] + ks*32);
            uint32_t bb[2][4];
#pragma unroll
            for (int p=0; p<2; p++)
                LDSM_X4(bb[p][0], bb[p][1], bb[p][2], bb[p][3],
                        sbk + bOff[p] + ks*32);
#pragma unroll
            for (int mt=0; mt<4; mt++)
#pragma unroll
                for (int nt=0; nt<4; nt++) {
                    const uint32_t b0 = bb[nt>>1][(nt&1)*2];
                    const uint32_t b1 = bb[nt>>1][(nt&1)*2+1];
                    MMA_BF16(acc[mt][nt][0], acc[mt][nt][1],
                             acc[mt][nt][2], acc[mt][nt][3],
                             a[mt][0], a[mt][1], a[mt][2], a[mt][3], b0, b1);
                }
        }

        // ---- prefetch stage it+2 (after first compute block) ----
        if (it + 2 < NPIX/BK) {
            const uint32_t slot = smBase + (uint32_t)slotP * (2*STGB);
            const char* sa = gAp + (size_t)(it+2) * (BK*2);
            const char* sb = gBp + (size_t)(it+2) * (BK*2);
#pragma unroll
            for (int j=0;j<4;j++) CP_ASYNC16(slot + ldOff + j*16, sa + j*16);
#pragma unroll
            for (int j=0;j<4;j++) CP_ASYNC16(slot + STGB + ldOff + j*16, sb + j*16);
        }
        CP_ASYNC_COMMIT();

        // ---- remaining ks blocks ----
#pragma unroll
        for (int ksi = 1; ksi < 4; ++ksi) {
            const int ks = (ksi + ko) & 3;
            uint32_t a[4][4];
#pragma unroll
            for (int mt=0; mt<4; mt++)
                LDSM_X4(a[mt][0], a[mt][1], a[mt][2], a[mt][3],
                        sbk + aOff[mt] + ks*32);
            uint32_t bb[2][4];
#pragma unroll
            for (int p=0; p<2; p++)
                LDSM_X4(bb[p][0], bb[p][1], bb[p][2], bb[p][3],
                        sbk + bOff[p] + ks*32);
#pragma unroll
            for (int mt=0; mt<4; mt++)
#pragma unroll
                for (int nt=0; nt<4; nt++) {
                    const uint32_t b0 = bb[nt>>1][(nt&1)*2];
                    const uint32_t b1 = bb[nt>>1][(nt&1)*2+1];
                    MMA_BF16(acc[mt][nt][0], acc[mt][nt][1],
                             acc[mt][nt][2], acc[mt][nt][3],
                             a[mt][0], a[mt][1], a[mt][2], a[mt][3], b0, b1);
                }
        }

        slotC = (slotC == 2) ? 0 : slotC + 1;
        slotP = (slotP == 2) ? 0 : slotP + 1;
    }

    const int g  = lane >> 2;
    const int tq = lane & 3;
    float* Cz = out + (size_t)z * CH * NPIX;
#pragma unroll
    for (int mt=0; mt<4; mt++) {
        const int row = cBase + warpM*64 + mt*16 + g;
#pragma unroll
        for (int nt=0; nt<4; nt++) {
            const int col = mBase + warpN*32 + nt*8 + tq*2;
            {
                const float2 xv = *reinterpret_cast<const float2*>(
                    &X[(size_t)row*NPIX + col]);
                float2 o;
                o.x = fmaf(gamma, acc[mt][nt][0], xv.x);
                o.y = fmaf(gamma, acc[mt][nt][1], xv.y);
                *reinterpret_cast<float2*>(&Cz[(size_t)row*NPIX + col]) = o;
            }
            {
                const float2 xv = *reinterpret_cast<const float2*>(
                    &X[(size_t)(row+8)*NPIX + col]);
                float2 o;
                o.x = fmaf(gamma, acc[mt][nt][2], xv.x);
                o.y = fmaf(gamma, acc[mt][nt][3], xv.y);
                *reinterpret_cast<float2*>(&Cz[(size_t)(row+8)*NPIX + col]) = o;
            }
        }
    }
}

// =====================================================================
extern "C" void kernel_launch(void* const* d_in, const int* in_sizes, int n_in,
                              void* d_out, int out_size)
{
    const float* x1     = (const float*)d_in[0];
    const float* x2     = (const float*)d_in[1];
    const float* f_w    = (const float*)d_in[2];
    const float* f_b    = (const float*)d_in[3];
    const float* g_w    = (const float*)d_in[4];
    const float* g_b    = (const float*)d_in[5];
    const float* h1_w   = (const float*)d_in[6];
    const float* h1_b   = (const float*)d_in[7];
    const float* h2_w   = (const float*)d_in[8];
    const float* h2_b   = (const float*)d_in[9];
    const float* gamma1 = (const float*)d_in[10];
    const float* gamma2 = (const float*)d_in[11];
    float* out = (float*)d_out;

    cudaFuncSetAttribute(fused_sm_kernel,
                         cudaFuncAttributeMaxDynamicSharedMemorySize, FSM_TOTAL);
    cudaFuncSetAttribute(proj_h_mma_kernel,
                         cudaFuncAttributeMaxDynamicSharedMemorySize, PH_SMEM);
    cudaFuncSetAttribute(out_mma_kernel,
                         cudaFuncAttributeMaxDynamicSharedMemorySize, OUT_SMEM);

    xt_kernel        <<<dim3(64, 4, NZ), 256>>>(x1, x2);
    proj_fg_kernel   <<<dim3(32, 2, NZ), 256>>>(x1, x2, f_w, f_b, g_w, g_b);
    fused_sm_kernel  <<<dim3(64, NZ), 256, FSM_TOTAL>>>();
    proj_h_mma_kernel<<<dim3(32, 4, NZ), 128, PH_SMEM>>>(h1_w, h1_b, h2_w, h2_b);
    out_mma_kernel   <<<dim3(32, 2, NZ), 256, OUT_SMEM>>>(x1, x2, gamma1, gamma2, out);
}

// round 10
// speedup vs baseline: 1.0200x; 1.0200x over previous
#include <cuda_runtime.h>
#include <cuda_bf16.h>
#include <cstdint>
#include <math.h>

#define NBATCH 4
#define CH     256
#define NPIX   4096
#define KD     32
#define NZ     8   // 2 branches x 4 batches

// ---- scratch (module-load allocated; no runtime alloc) ----
__device__ __nv_bfloat16 g_fT[NZ][NPIX][KD];         // f^T : [n][k] bf16
__device__ __nv_bfloat16 g_gT[NZ][NPIX][KD];         // g^T : [m][k] bf16
__device__ float         g_invsum[NZ][NPIX];         // 1 / softmax row sum (shifted)
__device__ __nv_bfloat16 g_Xt[NZ][NPIX][CH];         // x^T : [n][c] bf16
__device__ __nv_bfloat16 g_Wb[2][CH][CH];            // h weights, bf16
__device__ __nv_bfloat16 g_Hb[NZ][CH][NPIX];         // h projection (invsum-scaled), bf16
__device__ __nv_bfloat16 g_Pt[NZ][NPIX][NPIX];       // unnormalized P^T bf16: Pt[m][n]

__device__ __forceinline__ uint32_t smem_u32(const void* p) {
    uint32_t a;
    asm("{ .reg .u64 t; cvta.to.shared.u64 t, %1; cvt.u32.u64 %0, t; }" : "=r"(a) : "l"(p));
    return a;
}

__device__ __forceinline__ float ex2f(float x) {
    float r;
    asm("ex2.approx.f32 %0, %1;" : "=f"(r) : "f"(x));
    return r;
}

#define CP_ASYNC16(dst, src) \
    asm volatile("cp.async.cg.shared.global [%0], [%1], 16;" :: "r"(dst), "l"(src))
#define CP_ASYNC_COMMIT() asm volatile("cp.async.commit_group;" ::: "memory")
#define CP_ASYNC_WAIT_1() asm volatile("cp.async.wait_group 1;" ::: "memory")
#define CP_ASYNC_WAIT_0() asm volatile("cp.async.wait_group 0;" ::: "memory")

#define LDSM_X4(r0,r1,r2,r3,addr) \
    asm volatile("ldmatrix.sync.aligned.m8n8.x4.shared.b16 {%0,%1,%2,%3}, [%4];" \
        : "=r"(r0), "=r"(r1), "=r"(r2), "=r"(r3) : "r"(addr))

#define MMA_BF16(c0,c1,c2,c3,a0,a1,a2,a3,b0,b1) \
    asm volatile("mma.sync.aligned.m16n8k16.row.col.f32.bf16.bf16.f32 " \
        "{%0,%1,%2,%3}, {%4,%5,%6,%7}, {%8,%9}, {%0,%1,%2,%3};" \
        : "+f"(c0), "+f"(c1), "+f"(c2), "+f"(c3) \
        : "r"(a0), "r"(a1), "r"(a2), "r"(a3), "r"(b0), "r"(b1))

// =====================================================================
// SIMT SGEMM body (fp32) — used only for the small f/g projection.
// C is bf16 [Nglobal][KD], stores C[n][k] = acc^T.
// =====================================================================
template<int BM, int BN, int BK2, int TM, int TN>
__device__ __forceinline__ void sgemm_trans_body(
    const float* __restrict__ A, const float* __restrict__ B,
    __nv_bfloat16* __restrict__ C,
    int K, int ldA, int ldB,
    int tileCol,
    const float* __restrict__ bias)
{
    constexpr int THREADS = (BM/TM)*(BN/TN);
    __shared__ float As[BK2][BM];
    __shared__ float Bs[BK2][BN];
    const int tid = threadIdx.x;
    const int tx = tid % (BN/TN);
    const int ty = tid / (BN/TN);

    B += (size_t)tileCol * BN;

    constexpr int AVR = BK2/4;
    const int aRow = tid / AVR;
    const int aCol = (tid % AVR)*4;
    constexpr int ARS = THREADS / AVR;
    constexpr int AIT = BM / ARS;

    constexpr int BVR = BN/4;
    const int bRow = tid / BVR;
    const int bCol = (tid % BVR)*4;
    constexpr int BRS = THREADS / BVR;
    constexpr int BIT = BK2 / BRS;

    float4 aF[AIT], bF[BIT];
#pragma unroll
    for (int i=0;i<AIT;i++)
        aF[i] = *reinterpret_cast<const float4*>(&A[(size_t)(aRow+i*ARS)*ldA + aCol]);
#pragma unroll
    for (int i=0;i<BIT;i++)
        bF[i] = *reinterpret_cast<const float4*>(&B[(size_t)(bRow+i*BRS)*ldB + bCol]);

    float acc[TM][TN];
#pragma unroll
    for (int i=0;i<TM;i++)
#pragma unroll
        for (int j=0;j<TN;j++) acc[i][j] = 0.f;

    for (int kb = 0; kb < K; kb += BK2) {
        __syncthreads();
#pragma unroll
        for (int i=0;i<AIT;i++){
            As[aCol+0][aRow+i*ARS] = aF[i].x;
            As[aCol+1][aRow+i*ARS] = aF[i].y;
            As[aCol+2][aRow+i*ARS] = aF[i].z;
            As[aCol+3][aRow+i*ARS] = aF[i].w;
        }
#pragma unroll
        for (int i=0;i<BIT;i++)
            *reinterpret_cast<float4*>(&Bs[bRow+i*BRS][bCol]) = bF[i];
        __syncthreads();

        if (kb + BK2 < K) {
#pragma unroll
            for (int i=0;i<AIT;i++)
                aF[i] = *reinterpret_cast<const float4*>(
                    &A[(size_t)(aRow+i*ARS)*ldA + (kb+BK2) + aCol]);
#pragma unroll
            for (int i=0;i<BIT;i++)
                bF[i] = *reinterpret_cast<const float4*>(
                    &B[(size_t)(kb+BK2+bRow+i*BRS)*ldB + bCol]);
        }

#pragma unroll
        for (int k=0;k<BK2;k++){
            float ra[TM], rb[TN];
#pragma unroll
            for (int i=0;i<TM;i+=4){
                float4 v = *reinterpret_cast<const float4*>(&As[k][ty*TM+i]);
                ra[i]=v.x; ra[i+1]=v.y; ra[i+2]=v.z; ra[i+3]=v.w;
            }
#pragma unroll
            for (int j=0;j<TN;j+=4){
                float4 v = *reinterpret_cast<const float4*>(&Bs[k][tx*TN+j]);
                rb[j]=v.x; rb[j+1]=v.y; rb[j+2]=v.z; rb[j+3]=v.w;
            }
#pragma unroll
            for (int i=0;i<TM;i++)
#pragma unroll
                for (int j=0;j<TN;j++)
                    acc[i][j] = fmaf(ra[i], rb[j], acc[i][j]);
        }
    }

#pragma unroll
    for (int i=0;i<TM;i++){
        const int row = ty*TM + i;                 // k index
        const float bv = bias ? bias[row] : 0.f;
#pragma unroll
        for (int j=0;j<TN;j++){
            const int col = tileCol*BN + tx*TN + j;  // n index
            C[(size_t)col * KD + row] = __float2bfloat16(acc[i][j] + bv);
        }
    }
}

// =====================================================================
// Kernel W: convert h weights fp32 -> bf16.  grid 32, 256 threads.
// =====================================================================
__global__ __launch_bounds__(256) void wconv_kernel(
    const float* __restrict__ h1w, const float* __restrict__ h2w)
{
    const int idx = (blockIdx.x * 256 + threadIdx.x) * 8;   // 32*256*8 = 65536 per weight... x2 loop
#pragma unroll
    for (int w = 0; w < 2; ++w) {
        const float* src = (w ? h2w : h1w) + idx;
        __nv_bfloat16* dst = &g_Wb[w][0][0] + idx;
#pragma unroll
        for (int j = 0; j < 2; ++j) {
            const float4 v = *reinterpret_cast<const float4*>(src + j*4);
            __nv_bfloat162 p0 = __float22bfloat162_rn(make_float2(v.x, v.y));
            __nv_bfloat162 p1 = __float22bfloat162_rn(make_float2(v.z, v.w));
            uint2 u;
            u.x = reinterpret_cast<uint32_t&>(p0);
            u.y = reinterpret_cast<uint32_t&>(p1);
            *reinterpret_cast<uint2*>(dst + j*4) = u;
        }
    }
}

// =====================================================================
// Kernel 0: transpose x (fp32 [c][n]) -> Xt bf16 [n][c]
// =====================================================================
__global__ __launch_bounds__(256) void xt_kernel(
    const float* __restrict__ x1, const float* __restrict__ x2)
{
    const int z  = blockIdx.z;
    const int br = z >> 2, b = z & 3;
    const float* X = (br ? x2 : x1) + (size_t)b * CH * NPIX;
    const int n0 = blockIdx.x * 64;
    const int c0 = blockIdx.y * 64;

    __shared__ unsigned short t[64][66];
    const int tid = threadIdx.x;
    const int rr = tid >> 4;
    const int c4 = (tid & 15) * 4;

#pragma unroll
    for (int p=0;p<4;p++){
        const int crow = rr + p*16;
        const float4 v = *reinterpret_cast<const float4*>(
            &X[(size_t)(c0 + crow) * NPIX + n0 + c4]);
        t[crow][c4+0] = __bfloat16_as_ushort(__float2bfloat16(v.x));
        t[crow][c4+1] = __bfloat16_as_ushort(__float2bfloat16(v.y));
        t[crow][c4+2] = __bfloat16_as_ushort(__float2bfloat16(v.z));
        t[crow][c4+3] = __bfloat16_as_ushort(__float2bfloat16(v.w));
    }
    __syncthreads();

#pragma unroll
    for (int p=0;p<4;p++){
        const int nrow = rr + p*16;
        uint2 u;
        u.x = (uint32_t)t[c4+0][nrow] | ((uint32_t)t[c4+1][nrow] << 16);
        u.y = (uint32_t)t[c4+2][nrow] | ((uint32_t)t[c4+3][nrow] << 16);
        *reinterpret_cast<uint2*>(&g_Xt[z][n0 + nrow][c0 + c4]) = u;
    }
}

// =====================================================================
// Kernel 1: f/g projections -> transposed bf16 [n][32]
// =====================================================================
__global__ __launch_bounds__(256) void proj_fg_kernel(
    const float* __restrict__ x1, const float* __restrict__ x2,
    const float* __restrict__ f_w, const float* __restrict__ f_b,
    const float* __restrict__ g_w, const float* __restrict__ g_b)
{
    const int z  = blockIdx.z;
    const int br = z >> 2, b = z & 3;
    const int fg = blockIdx.y;
    const float* W    = fg ? g_w : f_w;
    const float* bias = fg ? g_b : f_b;
    const float* X    = (br ? x2 : x1) + (size_t)b * CH * NPIX;
    __nv_bfloat16* C = fg ? &g_gT[z][0][0] : &g_fT[z][0][0];
    sgemm_trans_body<32,128,32,4,4>(W, X, C, CH, CH, NPIX, blockIdx.x, bias);
}

// =====================================================================
// Kernel 2 (fused, single pass): scores (HMMA bf16) + fixed-shift exp +
// transposed bf16 P' write + shifted row sums.  (unchanged)
// =====================================================================
#define FLD   40
#define FSM_FT   0u
#define FSM_G    5120u
#define FSM_GSZ  20480u
#define FSM_ST   46080u
#define FSM_RED  82944u
#define FSM_TOTAL 83968u

__global__ __launch_bounds__(256) void fused_sm_kernel()
{
    extern __shared__ __align__(16) char sm[];
    const uint32_t smBase = smem_u32(sm);
    float* red = reinterpret_cast<float*>(sm + FSM_RED);

    const int tid  = threadIdx.x;
    const int lane = tid & 31, wid = tid >> 5;
    const int z  = blockIdx.y;
    const int n0 = blockIdx.x * 64;
    const int warpM = wid >> 2;
    const int warpN = wid & 3;
    const int qg = lane >> 2, tq = lane & 3;

    {
        const int row = tid >> 2, ch = tid & 3;
        CP_ASYNC16(smBase + FSM_FT + (uint32_t)((row*FLD + ch*8)*2),
                   (const char*)&g_fT[z][n0 + row][ch*8]);
    }
    CP_ASYNC_COMMIT();

    const int lm  = lane & 15;
    const int aco = (lane >= 16) ? 8 : 0;
    uint32_t aAddr[2];
#pragma unroll
    for (int mt=0; mt<2; mt++)
        aAddr[mt] = smBase + FSM_FT +
            (uint32_t)(((warpM*32 + mt*16 + lm)*FLD + aco)*2);
    const int bro = (lane & 7) + ((lane >= 16) ? 8 : 0);
    const int bco = (lane & 8) ? 8 : 0;
    uint32_t bOff[4];
#pragma unroll
    for (int p=0; p<4; p++)
        bOff[p] = (uint32_t)(((warpN*64 + p*16 + bro)*FLD + bco)*2);

    const int grow = tid >> 2, gch = tid & 3;

    float rsum[4];
#pragma unroll
    for (int i=0;i<4;i++) rsum[i] = 0.f;

    const float CEXP  = 0.17677669529663688f * 1.4426950408889634f;
    const float SHIFT = 16.0f * 1.4426950408889634f;

    {
        const char* src = (const char*)&g_gT[z][0][0];
#pragma unroll
        for (int i=0;i<4;i++)
            CP_ASYNC16(smBase + FSM_G + (uint32_t)(((grow+i*64)*FLD + gch*8)*2),
                       src + (size_t)(grow + i*64)*64 + gch*16);
        CP_ASYNC_COMMIT();
    }
    for (int t = 0; t < 16; ++t) {
        if (t < 15) {
            const uint32_t dst = smBase + FSM_G + (uint32_t)((t+1)&1)*FSM_GSZ;
            const char* src = (const char*)&g_gT[z][(t+1)*256][0];
#pragma unroll
            for (int i=0;i<4;i++)
                CP_ASYNC16(dst + (uint32_t)(((grow+i*64)*FLD + gch*8)*2),
                           src + (size_t)(grow + i*64)*64 + gch*16);
            CP_ASYNC_COMMIT();
            CP_ASYNC_WAIT_1();
        } else {
            CP_ASYNC_WAIT_0();
        }
        __syncthreads();

        const uint32_t gb = smBase + FSM_G + (uint32_t)(t&1)*FSM_GSZ;
        float acc[2][8][4];
#pragma unroll
        for (int mt=0;mt<2;mt++)
#pragma unroll
            for (int nt=0;nt<8;nt++)
#pragma unroll
                for (int c=0;c<4;c++) acc[mt][nt][c] = 0.f;

#pragma unroll
        for (int ks = 0; ks < 2; ++ks) {
            uint32_t a[2][4];
#pragma unroll
            for (int mt=0; mt<2; mt++)
                LDSM_X4(a[mt][0], a[mt][1], a[mt][2], a[mt][3],
                        aAddr[mt] + ks*32);
            uint32_t bb[4][4];
#pragma unroll
            for (int p=0; p<4; p++)
                LDSM_X4(bb[p][0], bb[p][1], bb[p][2], bb[p][3],
                        gb + bOff[p] + ks*32);
#pragma unroll
            for (int mt=0; mt<2; mt++)
#pragma unroll
                for (int nt=0; nt<8; nt++) {
                    const uint32_t b0 = bb[nt>>1][(nt&1)*2];
                    const uint32_t b1 = bb[nt>>1][(nt&1)*2+1];
                    MMA_BF16(acc[mt][nt][0], acc[mt][nt][1],
                             acc[mt][nt][2], acc[mt][nt][3],
                             a[mt][0], a[mt][1], a[mt][2], a[mt][3], b0, b1);
                }
        }

        {
            __nv_bfloat16* stg = reinterpret_cast<__nv_bfloat16*>(sm + FSM_ST);
#pragma unroll
            for (int mt=0;mt<2;mt++)
#pragma unroll
                for (int nt=0;nt<8;nt++)
#pragma unroll
                    for (int c=0;c<4;c++){
                        const int idx = mt*2 + (c>>1);
                        const float p = ex2f(fmaf(acc[mt][nt][c], CEXP, -SHIFT));
                        rsum[idx] += p;
                        const int ml = warpN*64 + nt*8 + tq*2 + (c&1);
                        const int nl = warpM*32 + mt*16 + qg + (c>>1)*8;
                        stg[ml*72 + nl] = __float2bfloat16(p);
                    }
            __syncthreads();
            const int ch = tid & 7;
#pragma unroll
            for (int i=0;i<8;i++){
                const int ml = (tid>>3) + i*32;
                const uint4 v = *reinterpret_cast<const uint4*>(
                    sm + FSM_ST + (uint32_t)((ml*72 + ch*8)*2));
                *reinterpret_cast<uint4*>(&g_Pt[z][t*256 + ml][n0 + ch*8]) = v;
            }
            __syncthreads();
        }
    }

#pragma unroll
    for (int i=0;i<4;i++){
        float v = rsum[i];
        v += __shfl_xor_sync(0xffffffffu, v, 1);
        v += __shfl_xor_sync(0xffffffffu, v, 2);
        rsum[i] = v;
    }
    if (tq == 0) {
#pragma unroll
        for (int i=0;i<4;i++){
            const int r = warpM*32 + (i>>1)*16 + qg + (i&1)*8;
            red[r*4 + warpN] = rsum[i];
        }
    }
    __syncthreads();
    if (warpN == 0 && tq == 0) {
#pragma unroll
        for (int i=0;i<4;i++){
            const int r = warpM*32 + (i>>1)*16 + qg + (i&1)*8;
            const float s = red[r*4+0] + red[r*4+1] + red[r*4+2] + red[r*4+3];
            g_invsum[z][n0 + r] = 1.0f / s;
        }
    }
}

// =====================================================================
// Kernel 3: h projection via HMMA, fully cp.async + K pipelined.
// CTA 64(o) x 128(n), 128 threads, 4 warps 64x32, K = 2 stages of 128.
// 2 CTAs/SM.  grid (32 n-tiles, 4 o-tiles, NZ) = 1024 CTAs.
// =====================================================================
#define PH_LDA   136                         // elems per stage row (128+8 pad); 272B
#define PH_AST   (64*PH_LDA*2)               // A per stage: 17408
#define PH_BST   (128*PH_LDA*2)              // B per stage: 34816
#define PH_STG   (PH_AST + PH_BST)           // 52224
#define PH_SMEM  (2*PH_STG)                  // 104448

__global__ void __launch_bounds__(128, 2) proj_h_mma_kernel(
    const float* __restrict__ h1b, const float* __restrict__ h2b)
{
    extern __shared__ char smh[];
    const uint32_t smBase = smem_u32(smh);

    const int tid = threadIdx.x;
    const int wid = tid >> 5, lane = tid & 31;
    const int z = blockIdx.z, br = z >> 2;
    const int nBase = blockIdx.x * 128;
    const int oBase = blockIdx.y * 64;
    const float* bias = br ? h2b : h1b;

    // loader mappings
    const int arow = tid >> 1;
    const int ahalf = (tid & 1) * 128;       // byte offset in 256B row
    const char* gA = (const char*)&g_Wb[br][oBase + arow][0] + ahalf;
    const uint32_t dA = (uint32_t)(arow * (PH_LDA*2) + ahalf);
    const char* gB = (const char*)&g_Xt[z][nBase + tid][0];
    const uint32_t dB = PH_AST + (uint32_t)(tid * (PH_LDA*2));

    // prologue: both stages
#pragma unroll
    for (int st = 0; st < 2; ++st) {
        const uint32_t slot = smBase + (uint32_t)st * PH_STG;
        const char* sa = gA + (size_t)st * 256;   // 128 bf16 = 256B per stage
        const char* sb = gB + (size_t)st * 256;
#pragma unroll
        for (int j=0;j<8;j++)  CP_ASYNC16(slot + dA + j*16, sa + j*16);
#pragma unroll
        for (int j=0;j<16;j++) CP_ASYNC16(slot + dB + j*16, sb + j*16);
        CP_ASYNC_COMMIT();
    }

    // ldmatrix lane offsets (within a stage)
    const int warpN = wid;               // 0..3
    const int lm  = lane & 15;
    const int aco = (lane >= 16) ? 8 : 0;
    uint32_t aOff[4];
#pragma unroll
    for (int mt=0; mt<4; mt++)
        aOff[mt] = (uint32_t)(((mt*16 + lm)*PH_LDA + aco)*2);
    const int bro = (lane & 7) + ((lane >= 16) ? 8 : 0);
    const int bco = (lane & 8) ? 8 : 0;
    uint32_t bOffA[2];
#pragma unroll
    for (int p=0; p<2; p++)
        bOffA[p] = PH_AST + (uint32_t)(((warpN*32 + p*16 + bro)*PH_LDA + bco)*2);

    float acc[4][4][4];
#pragma unroll
    for (int i=0;i<4;i++)
#pragma unroll
        for (int j=0;j<4;j++)
#pragma unroll
            for (int k=0;k<4;k++) acc[i][j][k] = 0.f;

#pragma unroll
    for (int st = 0; st < 2; ++st) {
        if (st == 0) CP_ASYNC_WAIT_1(); else CP_ASYNC_WAIT_0();
        __syncthreads();
        const uint32_t slot = smBase + (uint32_t)st * PH_STG;
#pragma unroll
        for (int ks = 0; ks < 8; ++ks) {
            uint32_t a[4][4];
#pragma unroll
            for (int mt=0; mt<4; mt++)
                LDSM_X4(a[mt][0], a[mt][1], a[mt][2], a[mt][3],
                        slot + aOff[mt] + ks*32);
            uint32_t bb[2][4];
#pragma unroll
            for (int p=0; p<2; p++)
                LDSM_X4(bb[p][0], bb[p][1], bb[p][2], bb[p][3],
                        slot + bOffA[p] + ks*32);
#pragma unroll
            for (int mt=0; mt<4; mt++)
#pragma unroll
                for (int nt=0; nt<4; nt++) {
                    const uint32_t b0 = bb[nt>>1][(nt&1)*2];
                    const uint32_t b1 = bb[nt>>1][(nt&1)*2+1];
                    MMA_BF16(acc[mt][nt][0], acc[mt][nt][1],
                             acc[mt][nt][2], acc[mt][nt][3],
                             a[mt][0], a[mt][1], a[mt][2], a[mt][3], b0, b1);
                }
        }
    }

    // epilogue: H' = (acc + bias[o]) * invsum[n] -> bf16
    const int g  = lane >> 2;
    const int tq = lane & 3;
#pragma unroll
    for (int mt=0; mt<4; mt++) {
        const int row0 = oBase + mt*16 + g;
        const float bv0 = bias[row0];
        const float bv8 = bias[row0 + 8];
#pragma unroll
        for (int nt=0; nt<4; nt++) {
            const int col = nBase + warpN*32 + nt*8 + tq*2;
            const float2 iv = *reinterpret_cast<const float2*>(&g_invsum[z][col]);
            {
                const float v0 = (acc[mt][nt][0] + bv0) * iv.x;
                const float v1 = (acc[mt][nt][1] + bv0) * iv.y;
                __nv_bfloat162 pk = __float22bfloat162_rn(make_float2(v0, v1));
                *reinterpret_cast<uint32_t*>(&g_Hb[z][row0][col]) =
                    reinterpret_cast<uint32_t&>(pk);
            }
            {
                const float v0 = (acc[mt][nt][2] + bv8) * iv.x;
                const float v1 = (acc[mt][nt][3] + bv8) * iv.y;
                __nv_bfloat162 pk = __float22bfloat162_rn(make_float2(v0, v1));
                *reinterpret_cast<uint32_t*>(&g_Hb[z][row0 + 8][col]) =
                    reinterpret_cast<uint32_t&>(pk);
            }
        }
    }
}

// =====================================================================
// Kernel 4: out[z] = gamma * (H' @ P') + x  via mma.sync bf16 (HMMA).
// Round-5 proven config (best measured): CTA 128x128, 8 warps 2x4,
// 3-stage cp.async ring, 2 CTAs/SM.
// =====================================================================
#define BK      64
#define LDSS    72
#define STGB    (128*LDSS*2)             // 18432 bytes per operand per stage
#define NSTG    3
#define OUT_SMEM (NSTG*2*STGB)           // 110592

__global__ void __launch_bounds__(256, 2) out_mma_kernel(
    const float* __restrict__ x1, const float* __restrict__ x2,
    const float* __restrict__ gamma1, const float* __restrict__ gamma2,
    float* __restrict__ out)
{
    extern __shared__ char smo[];
    const uint32_t smBase = smem_u32(smo);

    const int tid = threadIdx.x;
    const int wid = tid >> 5, lane = tid & 31;
    const int z = blockIdx.z, br = z >> 2, b = z & 3;
    const int mBase = blockIdx.x * 128;
    const int cBase = blockIdx.y * 128;
    const float* X = (br ? x2 : x1) + (size_t)b * CH * NPIX;
    const float gamma = (br ? gamma2 : gamma1)[0];

    const int lrow = tid >> 1;
    const int lcol = (tid & 1) * 32;
    const char* gAp = (const char*)(&g_Hb[z][cBase + lrow][lcol]);
    const char* gBp = (const char*)(&g_Pt[z][mBase + lrow][lcol]);
    const uint32_t ldOff = (uint32_t)((lrow*LDSS + lcol)*2);

    const int warpM = wid >> 2;
    const int warpN = wid & 3;
    const int lm  = lane & 15;
    const int aco = (lane >= 16) ? 8 : 0;
    uint32_t aOff[4];
#pragma unroll
    for (int mt=0; mt<4; mt++)
        aOff[mt] = (uint32_t)(((warpM*64 + mt*16 + lm)*LDSS + aco)*2);
    const int bro = (lane & 7) + ((lane >= 16) ? 8 : 0);
    const int bco = (lane & 8) ? 8 : 0;
    uint32_t bOff[2];
#pragma unroll
    for (int p=0; p<2; p++)
        bOff[p] = (uint32_t)(((warpN*32 + p*16 + bro)*LDSS + bco)*2) + STGB;

    float acc[4][4][4];
#pragma unroll
    for (int i=0;i<4;i++)
#pragma unroll
        for (int j=0;j<4;j++)
#pragma unroll
            for (int k=0;k<4;k++) acc[i][j][k] = 0.f;

#pragma unroll
    for (int st=0; st<2; ++st) {
        const uint32_t slot = smBase + (uint32_t)st * (2*STGB);
        const char* sa = gAp + (size_t)st * (BK*2);
        const char* sb = gBp + (size_t)st * (BK*2);
#pragma unroll
        for (int j=0;j<4;j++) CP_ASYNC16(slot + ldOff + j*16, sa + j*16);
#pragma unroll
        for (int j=0;j<4;j++) CP_ASYNC16(slot + STGB + ldOff + j*16, sb + j*16);
        CP_ASYNC_COMMIT();
    }

    int slotC = 0;
    int slotP = 2;
    for (int it = 0; it < NPIX/BK; ++it) {
        CP_ASYNC_WAIT_1();
        __syncthreads();

        if (it + 2 < NPIX/BK) {
            const uint32_t slot = smBase + (uint32_t)slotP * (2*STGB);
            const char* sa = gAp + (size_t)(it+2) * (BK*2);
            const char* sb = gBp + (size_t)(it+2) * (BK*2);
#pragma unroll
            for (int j=0;j<4;j++) CP_ASYNC16(slot + ldOff + j*16, sa + j*16);
#pragma unroll
            for (int j=0;j<4;j++) CP_ASYNC16(slot + STGB + ldOff + j*16, sb + j*16);
        }
        CP_ASYNC_COMMIT();

        const uint32_t sb = smBase + (uint32_t)slotC * (2*STGB);
#pragma unroll
        for (int ks = 0; ks < 4; ++ks) {
            uint32_t a[4][4];
#pragma unroll
            for (int mt=0; mt<4; mt++)
                LDSM_X4(a[mt][0], a[mt][1], a[mt][2], a[mt][3],
                        sb + aOff[mt] + ks*32);
            uint32_t bb[2][4];
#pragma unroll
            for (int p=0; p<2; p++)
                LDSM_X4(bb[p][0], bb[p][1], bb[p][2], bb[p][3],
                        sb + bOff[p] + ks*32);
#pragma unroll
            for (int mt=0; mt<4; mt++)
#pragma unroll
                for (int nt=0; nt<4; nt++) {
                    const uint32_t b0 = bb[nt>>1][(nt&1)*2];
                    const uint32_t b1 = bb[nt>>1][(nt&1)*2+1];
                    MMA_BF16(acc[mt][nt][0], acc[mt][nt][1],
                             acc[mt][nt][2], acc[mt][nt][3],
                             a[mt][0], a[mt][1], a[mt][2], a[mt][3], b0, b1);
                }
        }

        slotC = (slotC == 2) ? 0 : slotC + 1;
        slotP = (slotP == 2) ? 0 : slotP + 1;
    }

    const int g  = lane >> 2;
    const int tq = lane & 3;
    float* Cz = out + (size_t)z * CH * NPIX;
#pragma unroll
    for (int mt=0; mt<4; mt++) {
        const int row = cBase + warpM*64 + mt*16 + g;
#pragma unroll
        for (int nt=0; nt<4; nt++) {
            const int col = mBase + warpN*32 + nt*8 + tq*2;
            {
                const float2 xv = *reinterpret_cast<const float2*>(
                    &X[(size_t)row*NPIX + col]);
                float2 o;
                o.x = fmaf(gamma, acc[mt][nt][0], xv.x);
                o.y = fmaf(gamma, acc[mt][nt][1], xv.y);
                *reinterpret_cast<float2*>(&Cz[(size_t)row*NPIX + col]) = o;
            }
            {
                const float2 xv = *reinterpret_cast<const float2*>(
                    &X[(size_t)(row+8)*NPIX + col]);
                float2 o;
                o.x = fmaf(gamma, acc[mt][nt][2], xv.x);
                o.y = fmaf(gamma, acc[mt][nt][3], xv.y);
                *reinterpret_cast<float2*>(&Cz[(size_t)(row+8)*NPIX + col]) = o;
            }
        }
    }
}

// =====================================================================
extern "C" void kernel_launch(void* const* d_in, const int* in_sizes, int n_in,
                              void* d_out, int out_size)
{
    const float* x1     = (const float*)d_in[0];
    const float* x2     = (const float*)d_in[1];
    const float* f_w    = (const float*)d_in[2];
    const float* f_b    = (const float*)d_in[3];
    const float* g_w    = (const float*)d_in[4];
    const float* g_b    = (const float*)d_in[5];
    const float* h1_w   = (const float*)d_in[6];
    const float* h1_b   = (const float*)d_in[7];
    const float* h2_w   = (const float*)d_in[8];
    const float* h2_b   = (const float*)d_in[9];
    const float* gamma1 = (const float*)d_in[10];
    const float* gamma2 = (const float*)d_in[11];
    float* out = (float*)d_out;

    cudaFuncSetAttribute(fused_sm_kernel,
                         cudaFuncAttributeMaxDynamicSharedMemorySize, FSM_TOTAL);
    cudaFuncSetAttribute(proj_h_mma_kernel,
                         cudaFuncAttributeMaxDynamicSharedMemorySize, PH_SMEM);
    cudaFuncSetAttribute(out_mma_kernel,
                         cudaFuncAttributeMaxDynamicSharedMemorySize, OUT_SMEM);

    wconv_kernel     <<<32, 256>>>(h1_w, h2_w);
    xt_kernel        <<<dim3(64, 4, NZ), 256>>>(x1, x2);
    proj_fg_kernel   <<<dim3(32, 2, NZ), 256>>>(x1, x2, f_w, f_b, g_w, g_b);
    fused_sm_kernel  <<<dim3(64, NZ), 256, FSM_TOTAL>>>();
    proj_h_mma_kernel<<<dim3(32, 4, NZ), 128, PH_SMEM>>>(h1_b, h2_b);
    out_mma_kernel   <<<dim3(32, 2, NZ), 256, OUT_SMEM>>>(x1, x2, gamma1, gamma2, out);
}

// round 11
// speedup vs baseline: 1.0448x; 1.0243x over previous
#include <cuda_runtime.h>
#include <cuda_bf16.h>
#include <cstdint>
#include <math.h>

#define NBATCH 4
#define CH     256
#define NPIX   4096
#define KD     32
#define NZ     8   // 2 branches x 4 batches

// ---- scratch (module-load allocated; no runtime alloc) ----
__device__ __nv_bfloat16 g_fT[NZ][NPIX][KD];         // f^T : [n][k] bf16
__device__ __nv_bfloat16 g_gT[NZ][NPIX][KD];         // g^T : [m][k] bf16
__device__ float         g_invsum[NZ][NPIX];         // 1 / softmax row sum (shifted)
__device__ __nv_bfloat16 g_Xt[NZ][NPIX][CH];         // x^T : [n][c] bf16
__device__ __nv_bfloat16 g_Wb[2][CH][CH];            // h weights, bf16
__device__ __nv_bfloat16 g_Hb[NZ][CH][NPIX];         // h projection (invsum-scaled), bf16
__device__ __nv_bfloat16 g_Pt[NZ][NPIX][NPIX];       // unnormalized P^T bf16: Pt[m][n]

__device__ __forceinline__ uint32_t smem_u32(const void* p) {
    uint32_t a;
    asm("{ .reg .u64 t; cvta.to.shared.u64 t, %1; cvt.u32.u64 %0, t; }" : "=r"(a) : "l"(p));
    return a;
}

__device__ __forceinline__ float ex2f(float x) {
    float r;
    asm("ex2.approx.f32 %0, %1;" : "=f"(r) : "f"(x));
    return r;
}

#define CP_ASYNC16(dst, src) \
    asm volatile("cp.async.cg.shared.global [%0], [%1], 16;" :: "r"(dst), "l"(src))
#define CP_ASYNC_COMMIT() asm volatile("cp.async.commit_group;" ::: "memory")
#define CP_ASYNC_WAIT_1() asm volatile("cp.async.wait_group 1;" ::: "memory")
#define CP_ASYNC_WAIT_0() asm volatile("cp.async.wait_group 0;" ::: "memory")

#define LDSM_X4(r0,r1,r2,r3,addr) \
    asm volatile("ldmatrix.sync.aligned.m8n8.x4.shared.b16 {%0,%1,%2,%3}, [%4];" \
        : "=r"(r0), "=r"(r1), "=r"(r2), "=r"(r3) : "r"(addr))

#define STSM_X2_TRANS(addr, r0, r1) \
    asm volatile("stmatrix.sync.aligned.m8n8.x2.trans.shared.b16 [%0], {%1, %2};" \
        :: "r"(addr), "r"(r0), "r"(r1) : "memory")

#define MMA_BF16(c0,c1,c2,c3,a0,a1,a2,a3,b0,b1) \
    asm volatile("mma.sync.aligned.m16n8k16.row.col.f32.bf16.bf16.f32 " \
        "{%0,%1,%2,%3}, {%4,%5,%6,%7}, {%8,%9}, {%0,%1,%2,%3};" \
        : "+f"(c0), "+f"(c1), "+f"(c2), "+f"(c3) \
        : "r"(a0), "r"(a1), "r"(a2), "r"(a3), "r"(b0), "r"(b1))

// =====================================================================
// SIMT SGEMM body (fp32) — f/g projection only.
// C is bf16 [Nglobal][KD], stores C[n][k] = acc^T.
// =====================================================================
template<int BM, int BN, int BK2, int TM, int TN>
__device__ __forceinline__ void sgemm_trans_body(
    const float* __restrict__ A, const float* __restrict__ B,
    __nv_bfloat16* __restrict__ C,
    int K, int ldA, int ldB,
    int tileCol,
    const float* __restrict__ bias)
{
    constexpr int THREADS = (BM/TM)*(BN/TN);
    __shared__ float As[BK2][BM];
    __shared__ float Bs[BK2][BN];
    const int tid = threadIdx.x;
    const int tx = tid % (BN/TN);
    const int ty = tid / (BN/TN);

    B += (size_t)tileCol * BN;

    constexpr int AVR = BK2/4;
    const int aRow = tid / AVR;
    const int aCol = (tid % AVR)*4;
    constexpr int ARS = THREADS / AVR;
    constexpr int AIT = BM / ARS;

    constexpr int BVR = BN/4;
    const int bRow = tid / BVR;
    const int bCol = (tid % BVR)*4;
    constexpr int BRS = THREADS / BVR;
    constexpr int BIT = BK2 / BRS;

    float4 aF[AIT], bF[BIT];
#pragma unroll
    for (int i=0;i<AIT;i++)
        aF[i] = *reinterpret_cast<const float4*>(&A[(size_t)(aRow+i*ARS)*ldA + aCol]);
#pragma unroll
    for (int i=0;i<BIT;i++)
        bF[i] = *reinterpret_cast<const float4*>(&B[(size_t)(bRow+i*BRS)*ldB + bCol]);

    float acc[TM][TN];
#pragma unroll
    for (int i=0;i<TM;i++)
#pragma unroll
        for (int j=0;j<TN;j++) acc[i][j] = 0.f;

    for (int kb = 0; kb < K; kb += BK2) {
        __syncthreads();
#pragma unroll
        for (int i=0;i<AIT;i++){
            As[aCol+0][aRow+i*ARS] = aF[i].x;
            As[aCol+1][aRow+i*ARS] = aF[i].y;
            As[aCol+2][aRow+i*ARS] = aF[i].z;
            As[aCol+3][aRow+i*ARS] = aF[i].w;
        }
#pragma unroll
        for (int i=0;i<BIT;i++)
            *reinterpret_cast<float4*>(&Bs[bRow+i*BRS][bCol]) = bF[i];
        __syncthreads();

        if (kb + BK2 < K) {
#pragma unroll
            for (int i=0;i<AIT;i++)
                aF[i] = *reinterpret_cast<const float4*>(
                    &A[(size_t)(aRow+i*ARS)*ldA + (kb+BK2) + aCol]);
#pragma unroll
            for (int i=0;i<BIT;i++)
                bF[i] = *reinterpret_cast<const float4*>(
                    &B[(size_t)(kb+BK2+bRow+i*BRS)*ldB + bCol]);
        }

#pragma unroll
        for (int k=0;k<BK2;k++){
            float ra[TM], rb[TN];
#pragma unroll
            for (int i=0;i<TM;i+=4){
                float4 v = *reinterpret_cast<const float4*>(&As[k][ty*TM+i]);
                ra[i]=v.x; ra[i+1]=v.y; ra[i+2]=v.z; ra[i+3]=v.w;
            }
#pragma unroll
            for (int j=0;j<TN;j+=4){
                float4 v = *reinterpret_cast<const float4*>(&Bs[k][tx*TN+j]);
                rb[j]=v.x; rb[j+1]=v.y; rb[j+2]=v.z; rb[j+3]=v.w;
            }
#pragma unroll
            for (int i=0;i<TM;i++)
#pragma unroll
                for (int j=0;j<TN;j++)
                    acc[i][j] = fmaf(ra[i], rb[j], acc[i][j]);
        }
    }

#pragma unroll
    for (int i=0;i<TM;i++){
        const int row = ty*TM + i;                 // k index
        const float bv = bias ? bias[row] : 0.f;
#pragma unroll
        for (int j=0;j<TN;j++){
            const int col = tileCol*BN + tx*TN + j;  // n index
            C[(size_t)col * KD + row] = __float2bfloat16(acc[i][j] + bv);
        }
    }
}

// =====================================================================
// Kernel P (merged prep): xt transpose (2048 blocks) + f/g projection
// (512 blocks) + weight convert (32 blocks).  grid 2592, 256 threads.
// All three are mutually independent.
// =====================================================================
#define XT_BLKS 2048
#define FG_BLKS 512
#define WC_BLKS 32

__global__ __launch_bounds__(256) void prep_kernel(
    const float* __restrict__ x1, const float* __restrict__ x2,
    const float* __restrict__ f_w, const float* __restrict__ f_b,
    const float* __restrict__ g_w, const float* __restrict__ g_b,
    const float* __restrict__ h1w, const float* __restrict__ h2w)
{
    const int bx = blockIdx.x;
    const int tid = threadIdx.x;

    if (bx < XT_BLKS) {
        // ---- xt: transpose x fp32 [c][n] -> Xt bf16 [n][c] ----
        const int z  = bx >> 8;
        const int ct = (bx >> 6) & 3;
        const int nt = bx & 63;
        const int br = z >> 2, b = z & 3;
        const float* X = (br ? x2 : x1) + (size_t)b * CH * NPIX;
        const int n0 = nt * 64;
        const int c0 = ct * 64;

        __shared__ unsigned short t[64][66];
        const int rr = tid >> 4;
        const int c4 = (tid & 15) * 4;

#pragma unroll
        for (int p=0;p<4;p++){
            const int crow = rr + p*16;
            const float4 v = *reinterpret_cast<const float4*>(
                &X[(size_t)(c0 + crow) * NPIX + n0 + c4]);
            t[crow][c4+0] = __bfloat16_as_ushort(__float2bfloat16(v.x));
            t[crow][c4+1] = __bfloat16_as_ushort(__float2bfloat16(v.y));
            t[crow][c4+2] = __bfloat16_as_ushort(__float2bfloat16(v.z));
            t[crow][c4+3] = __bfloat16_as_ushort(__float2bfloat16(v.w));
        }
        __syncthreads();

#pragma unroll
        for (int p=0;p<4;p++){
            const int nrow = rr + p*16;
            uint2 u;
            u.x = (uint32_t)t[c4+0][nrow] | ((uint32_t)t[c4+1][nrow] << 16);
            u.y = (uint32_t)t[c4+2][nrow] | ((uint32_t)t[c4+3][nrow] << 16);
            *reinterpret_cast<uint2*>(&g_Xt[z][n0 + nrow][c0 + c4]) = u;
        }
    } else if (bx < XT_BLKS + FG_BLKS) {
        // ---- f/g projections -> transposed bf16 [n][32] ----
        const int idx = bx - XT_BLKS;
        const int z  = idx >> 6;
        const int fg = (idx >> 5) & 1;
        const int xt = idx & 31;
        const int br = z >> 2, b = z & 3;
        const float* W    = fg ? g_w : f_w;
        const float* bias = fg ? g_b : f_b;
        const float* X    = (br ? x2 : x1) + (size_t)b * CH * NPIX;
        __nv_bfloat16* C = fg ? &g_gT[z][0][0] : &g_fT[z][0][0];
        sgemm_trans_body<32,128,32,4,4>(W, X, C, CH, CH, NPIX, xt, bias);
    } else {
        // ---- weight convert fp32 -> bf16 ----
        const int idx = ((bx - XT_BLKS - FG_BLKS) * 256 + tid) * 8;
#pragma unroll
        for (int w = 0; w < 2; ++w) {
            const float* src = (w ? h2w : h1w) + idx;
            __nv_bfloat16* dst = &g_Wb[w][0][0] + idx;
#pragma unroll
            for (int j = 0; j < 2; ++j) {
                const float4 v = *reinterpret_cast<const float4*>(src + j*4);
                __nv_bfloat162 p0 = __float22bfloat162_rn(make_float2(v.x, v.y));
                __nv_bfloat162 p1 = __float22bfloat162_rn(make_float2(v.z, v.w));
                uint2 u;
                u.x = reinterpret_cast<uint32_t&>(p0);
                u.y = reinterpret_cast<uint32_t&>(p1);
                *reinterpret_cast<uint2*>(dst + j*4) = u;
            }
        }
    }
}

// =====================================================================
// Kernel 2 (fused, single pass): scores (HMMA bf16) + fixed-shift exp +
// stmatrix.trans transposed bf16 P' staging + shifted row sums.
// =====================================================================
#define FLD   40
#define FSM_FT   0u
#define FSM_G    5120u
#define FSM_GSZ  20480u
#define FSM_ST   46080u
#define FSM_RED  82944u
#define FSM_TOTAL 83968u

__global__ __launch_bounds__(256) void fused_sm_kernel()
{
    extern __shared__ __align__(16) char sm[];
    const uint32_t smBase = smem_u32(sm);
    float* red = reinterpret_cast<float*>(sm + FSM_RED);

    const int tid  = threadIdx.x;
    const int lane = tid & 31, wid = tid >> 5;
    const int z  = blockIdx.y;
    const int n0 = blockIdx.x * 64;
    const int warpM = wid >> 2;
    const int warpN = wid & 3;
    const int qg = lane >> 2, tq = lane & 3;

    {
        const int row = tid >> 2, ch = tid & 3;
        CP_ASYNC16(smBase + FSM_FT + (uint32_t)((row*FLD + ch*8)*2),
                   (const char*)&g_fT[z][n0 + row][ch*8]);
    }
    CP_ASYNC_COMMIT();

    const int lm  = lane & 15;
    const int aco = (lane >= 16) ? 8 : 0;
    uint32_t aAddr[2];
#pragma unroll
    for (int mt=0; mt<2; mt++)
        aAddr[mt] = smBase + FSM_FT +
            (uint32_t)(((warpM*32 + mt*16 + lm)*FLD + aco)*2);
    const int bro = (lane & 7) + ((lane >= 16) ? 8 : 0);
    const int bco = (lane & 8) ? 8 : 0;
    uint32_t bOff[4];
#pragma unroll
    for (int p=0; p<4; p++)
        bOff[p] = (uint32_t)(((warpN*64 + p*16 + bro)*FLD + bco)*2);

    const int grow = tid >> 2, gch = tid & 3;

    // stmatrix lane base: row (lane&7) of the stored (transposed) tile;
    // lanes 8..15 handle the second 8x8 (n offset +8).
    const uint32_t stLane = smBase + FSM_ST +
        (uint32_t)(((lane & 7) * 72 + ((lane & 8) ? 8 : 0)) * 2);

    float rsum[4];
#pragma unroll
    for (int i=0;i<4;i++) rsum[i] = 0.f;

    const float CEXP  = 0.17677669529663688f * 1.4426950408889634f;
    const float SHIFT = 16.0f * 1.4426950408889634f;

    {
        const char* src = (const char*)&g_gT[z][0][0];
#pragma unroll
        for (int i=0;i<4;i++)
            CP_ASYNC16(smBase + FSM_G + (uint32_t)(((grow+i*64)*FLD + gch*8)*2),
                       src + (size_t)(grow + i*64)*64 + gch*16);
        CP_ASYNC_COMMIT();
    }
    for (int t = 0; t < 16; ++t) {
        if (t < 15) {
            const uint32_t dst = smBase + FSM_G + (uint32_t)((t+1)&1)*FSM_GSZ;
            const char* src = (const char*)&g_gT[z][(t+1)*256][0];
#pragma unroll
            for (int i=0;i<4;i++)
                CP_ASYNC16(dst + (uint32_t)(((grow+i*64)*FLD + gch*8)*2),
                           src + (size_t)(grow + i*64)*64 + gch*16);
            CP_ASYNC_COMMIT();
            CP_ASYNC_WAIT_1();
        } else {
            CP_ASYNC_WAIT_0();
        }
        __syncthreads();

        const uint32_t gb = smBase + FSM_G + (uint32_t)(t&1)*FSM_GSZ;
        float acc[2][8][4];
#pragma unroll
        for (int mt=0;mt<2;mt++)
#pragma unroll
            for (int nt=0;nt<8;nt++)
#pragma unroll
                for (int c=0;c<4;c++) acc[mt][nt][c] = 0.f;

#pragma unroll
        for (int ks = 0; ks < 2; ++ks) {
            uint32_t a[2][4];
#pragma unroll
            for (int mt=0; mt<2; mt++)
                LDSM_X4(a[mt][0], a[mt][1], a[mt][2], a[mt][3],
                        aAddr[mt] + ks*32);
            uint32_t bb[4][4];
#pragma unroll
            for (int p=0; p<4; p++)
                LDSM_X4(bb[p][0], bb[p][1], bb[p][2], bb[p][3],
                        gb + bOff[p] + ks*32);
#pragma unroll
            for (int mt=0; mt<2; mt++)
#pragma unroll
                for (int nt=0; nt<8; nt++) {
                    const uint32_t b0 = bb[nt>>1][(nt&1)*2];
                    const uint32_t b1 = bb[nt>>1][(nt&1)*2+1];
                    MMA_BF16(acc[mt][nt][0], acc[mt][nt][1],
                             acc[mt][nt][2], acc[mt][nt][3],
                             a[mt][0], a[mt][1], a[mt][2], a[mt][3], b0, b1);
                }
        }

        // ---- exp + stmatrix.trans staging + row sums ----
        {
#pragma unroll
            for (int mt=0;mt<2;mt++)
#pragma unroll
                for (int nt=0;nt<8;nt++){
                    const float p0 = ex2f(fmaf(acc[mt][nt][0], CEXP, -SHIFT));
                    const float p1 = ex2f(fmaf(acc[mt][nt][1], CEXP, -SHIFT));
                    const float p2 = ex2f(fmaf(acc[mt][nt][2], CEXP, -SHIFT));
                    const float p3 = ex2f(fmaf(acc[mt][nt][3], CEXP, -SHIFT));
                    rsum[mt*2+0] += p0 + p1;
                    rsum[mt*2+1] += p2 + p3;
                    __nv_bfloat162 q0 = __float22bfloat162_rn(make_float2(p0, p1));
                    __nv_bfloat162 q1 = __float22bfloat162_rn(make_float2(p2, p3));
                    const uint32_t addr = stLane +
                        (uint32_t)(((warpN*64 + nt*8)*72 + warpM*32 + mt*16) * 2);
                    STSM_X2_TRANS(addr,
                                  reinterpret_cast<uint32_t&>(q0),
                                  reinterpret_cast<uint32_t&>(q1));
                }
            __syncthreads();
            const int ch = tid & 7;
#pragma unroll
            for (int i=0;i<8;i++){
                const int ml = (tid>>3) + i*32;
                const uint4 v = *reinterpret_cast<const uint4*>(
                    sm + FSM_ST + (uint32_t)((ml*72 + ch*8)*2));
                *reinterpret_cast<uint4*>(&g_Pt[z][t*256 + ml][n0 + ch*8]) = v;
            }
            __syncthreads();
        }
    }

#pragma unroll
    for (int i=0;i<4;i++){
        float v = rsum[i];
        v += __shfl_xor_sync(0xffffffffu, v, 1);
        v += __shfl_xor_sync(0xffffffffu, v, 2);
        rsum[i] = v;
    }
    if (tq == 0) {
#pragma unroll
        for (int i=0;i<4;i++){
            const int r = warpM*32 + (i>>1)*16 + qg + (i&1)*8;
            red[r*4 + warpN] = rsum[i];
        }
    }
    __syncthreads();
    if (warpN == 0 && tq == 0) {
#pragma unroll
        for (int i=0;i<4;i++){
            const int r = warpM*32 + (i>>1)*16 + qg + (i&1)*8;
            const float s = red[r*4+0] + red[r*4+1] + red[r*4+2] + red[r*4+3];
            g_invsum[z][n0 + r] = 1.0f / s;
        }
    }
}

// =====================================================================
// Kernel 3: h projection via HMMA, fully cp.async + K pipelined.
// CTA 64(o) x 128(n), 128 threads, 4 warps 64x32, K = 2 stages of 128.
// =====================================================================
#define PH_LDA   136
#define PH_AST   (64*PH_LDA*2)
#define PH_BST   (128*PH_LDA*2)
#define PH_STG   (PH_AST + PH_BST)
#define PH_SMEM  (2*PH_STG)

__global__ void __launch_bounds__(128, 2) proj_h_mma_kernel(
    const float* __restrict__ h1b, const float* __restrict__ h2b)
{
    extern __shared__ char smh[];
    const uint32_t smBase = smem_u32(smh);

    const int tid = threadIdx.x;
    const int wid = tid >> 5, lane = tid & 31;
    const int z = blockIdx.z, br = z >> 2;
    const int nBase = blockIdx.x * 128;
    const int oBase = blockIdx.y * 64;
    const float* bias = br ? h2b : h1b;

    const int arow = tid >> 1;
    const int ahalf = (tid & 1) * 128;
    const char* gA = (const char*)&g_Wb[br][oBase + arow][0] + ahalf;
    const uint32_t dA = (uint32_t)(arow * (PH_LDA*2) + ahalf);
    const char* gB = (const char*)&g_Xt[z][nBase + tid][0];
    const uint32_t dB = PH_AST + (uint32_t)(tid * (PH_LDA*2));

#pragma unroll
    for (int st = 0; st < 2; ++st) {
        const uint32_t slot = smBase + (uint32_t)st * PH_STG;
        const char* sa = gA + (size_t)st * 256;
        const char* sb = gB + (size_t)st * 256;
#pragma unroll
        for (int j=0;j<8;j++)  CP_ASYNC16(slot + dA + j*16, sa + j*16);
#pragma unroll
        for (int j=0;j<16;j++) CP_ASYNC16(slot + dB + j*16, sb + j*16);
        CP_ASYNC_COMMIT();
    }

    const int warpN = wid;
    const int lm  = lane & 15;
    const int aco = (lane >= 16) ? 8 : 0;
    uint32_t aOff[4];
#pragma unroll
    for (int mt=0; mt<4; mt++)
        aOff[mt] = (uint32_t)(((mt*16 + lm)*PH_LDA + aco)*2);
    const int bro = (lane & 7) + ((lane >= 16) ? 8 : 0);
    const int bco = (lane & 8) ? 8 : 0;
    uint32_t bOffA[2];
#pragma unroll
    for (int p=0; p<2; p++)
        bOffA[p] = PH_AST + (uint32_t)(((warpN*32 + p*16 + bro)*PH_LDA + bco)*2);

    float acc[4][4][4];
#pragma unroll
    for (int i=0;i<4;i++)
#pragma unroll
        for (int j=0;j<4;j++)
#pragma unroll
            for (int k=0;k<4;k++) acc[i][j][k] = 0.f;

#pragma unroll
    for (int st = 0; st < 2; ++st) {
        if (st == 0) CP_ASYNC_WAIT_1(); else CP_ASYNC_WAIT_0();
        __syncthreads();
        const uint32_t slot = smBase + (uint32_t)st * PH_STG;
#pragma unroll
        for (int ks = 0; ks < 8; ++ks) {
            uint32_t a[4][4];
#pragma unroll
            for (int mt=0; mt<4; mt++)
                LDSM_X4(a[mt][0], a[mt][1], a[mt][2], a[mt][3],
                        slot + aOff[mt] + ks*32);
            uint32_t bb[2][4];
#pragma unroll
            for (int p=0; p<2; p++)
                LDSM_X4(bb[p][0], bb[p][1], bb[p][2], bb[p][3],
                        slot + bOffA[p] + ks*32);
#pragma unroll
            for (int mt=0; mt<4; mt++)
#pragma unroll
                for (int nt=0; nt<4; nt++) {
                    const uint32_t b0 = bb[nt>>1][(nt&1)*2];
                    const uint32_t b1 = bb[nt>>1][(nt&1)*2+1];
                    MMA_BF16(acc[mt][nt][0], acc[mt][nt][1],
                             acc[mt][nt][2], acc[mt][nt][3],
                             a[mt][0], a[mt][1], a[mt][2], a[mt][3], b0, b1);
                }
        }
    }

    const int g  = lane >> 2;
    const int tq = lane & 3;
#pragma unroll
    for (int mt=0; mt<4; mt++) {
        const int row0 = oBase + mt*16 + g;
        const float bv0 = bias[row0];
        const float bv8 = bias[row0 + 8];
#pragma unroll
        for (int nt=0; nt<4; nt++) {
            const int col = nBase + warpN*32 + nt*8 + tq*2;
            const float2 iv = *reinterpret_cast<const float2*>(&g_invsum[z][col]);
            {
                const float v0 = (acc[mt][nt][0] + bv0) * iv.x;
                const float v1 = (acc[mt][nt][1] + bv0) * iv.y;
                __nv_bfloat162 pk = __float22bfloat162_rn(make_float2(v0, v1));
                *reinterpret_cast<uint32_t*>(&g_Hb[z][row0][col]) =
                    reinterpret_cast<uint32_t&>(pk);
            }
            {
                const float v0 = (acc[mt][nt][2] + bv8) * iv.x;
                const float v1 = (acc[mt][nt][3] + bv8) * iv.y;
                __nv_bfloat162 pk = __float22bfloat162_rn(make_float2(v0, v1));
                *reinterpret_cast<uint32_t*>(&g_Hb[z][row0 + 8][col]) =
                    reinterpret_cast<uint32_t&>(pk);
            }
        }
    }
}

// =====================================================================
// Kernel 4: out[z] = gamma * (H' @ P') + x  via mma.sync bf16 (HMMA).
// Round-5 proven config (frozen).
// =====================================================================
#define BK      64
#define LDSS    72
#define STGB    (128*LDSS*2)
#define NSTG    3
#define OUT_SMEM (NSTG*2*STGB)

__global__ void __launch_bounds__(256, 2) out_mma_kernel(
    const float* __restrict__ x1, const float* __restrict__ x2,
    const float* __restrict__ gamma1, const float* __restrict__ gamma2,
    float* __restrict__ out)
{
    extern __shared__ char smo[];
    const uint32_t smBase = smem_u32(smo);

    const int tid = threadIdx.x;
    const int wid = tid >> 5, lane = tid & 31;
    const int z = blockIdx.z, br = z >> 2, b = z & 3;
    const int mBase = blockIdx.x * 128;
    const int cBase = blockIdx.y * 128;
    const float* X = (br ? x2 : x1) + (size_t)b * CH * NPIX;
    const float gamma = (br ? gamma2 : gamma1)[0];

    const int lrow = tid >> 1;
    const int lcol = (tid & 1) * 32;
    const char* gAp = (const char*)(&g_Hb[z][cBase + lrow][lcol]);
    const char* gBp = (const char*)(&g_Pt[z][mBase + lrow][lcol]);
    const uint32_t ldOff = (uint32_t)((lrow*LDSS + lcol)*2);

    const int warpM = wid >> 2;
    const int warpN = wid & 3;
    const int lm  = lane & 15;
    const int aco = (lane >= 16) ? 8 : 0;
    uint32_t aOff[4];
#pragma unroll
    for (int mt=0; mt<4; mt++)
        aOff[mt] = (uint32_t)(((warpM*64 + mt*16 + lm)*LDSS + aco)*2);
    const int bro = (lane & 7) + ((lane >= 16) ? 8 : 0);
    const int bco = (lane & 8) ? 8 : 0;
    uint32_t bOff[2];
#pragma unroll
    for (int p=0; p<2; p++)
        bOff[p] = (uint32_t)(((warpN*32 + p*16 + bro)*LDSS + bco)*2) + STGB;

    float acc[4][4][4];
#pragma unroll
    for (int i=0;i<4;i++)
#pragma unroll
        for (int j=0;j<4;j++)
#pragma unroll
            for (int k=0;k<4;k++) acc[i][j][k] = 0.f;

#pragma unroll
    for (int st=0; st<2; ++st) {
        const uint32_t slot = smBase + (uint32_t)st * (2*STGB);
        const char* sa = gAp + (size_t)st * (BK*2);
        const char* sb = gBp + (size_t)st * (BK*2);
#pragma unroll
        for (int j=0;j<4;j++) CP_ASYNC16(slot + ldOff + j*16, sa + j*16);
#pragma unroll
        for (int j=0;j<4;j++) CP_ASYNC16(slot + STGB + ldOff + j*16, sb + j*16);
        CP_ASYNC_COMMIT();
    }

    int slotC = 0;
    int slotP = 2;
    for (int it = 0; it < NPIX/BK; ++it) {
        CP_ASYNC_WAIT_1();
        __syncthreads();

        if (it + 2 < NPIX/BK) {
            const uint32_t slot = smBase + (uint32_t)slotP * (2*STGB);
            const char* sa = gAp + (size_t)(it+2) * (BK*2);
            const char* sb = gBp + (size_t)(it+2) * (BK*2);
#pragma unroll
            for (int j=0;j<4;j++) CP_ASYNC16(slot + ldOff + j*16, sa + j*16);
#pragma unroll
            for (int j=0;j<4;j++) CP_ASYNC16(slot + STGB + ldOff + j*16, sb + j*16);
        }
        CP_ASYNC_COMMIT();

        const uint32_t sb = smBase + (uint32_t)slotC * (2*STGB);
#pragma unroll
        for (int ks = 0; ks < 4; ++ks) {
            uint32_t a[4][4];
#pragma unroll
            for (int mt=0; mt<4; mt++)
                LDSM_X4(a[mt][0], a[mt][1], a[mt][2], a[mt][3],
                        sb + aOff[mt] + ks*32);
            uint32_t bb[2][4];
#pragma unroll
            for (int p=0; p<2; p++)
                LDSM_X4(bb[p][0], bb[p][1], bb[p][2], bb[p][3],
                        sb + bOff[p] + ks*32);
#pragma unroll
            for (int mt=0; mt<4; mt++)
#pragma unroll
                for (int nt=0; nt<4; nt++) {
                    const uint32_t b0 = bb[nt>>1][(nt&1)*2];
                    const uint32_t b1 = bb[nt>>1][(nt&1)*2+1];
                    MMA_BF16(acc[mt][nt][0], acc[mt][nt][1],
                             acc[mt][nt][2], acc[mt][nt][3],
                             a[mt][0], a[mt][1], a[mt][2], a[mt][3], b0, b1);
                }
        }

        slotC = (slotC == 2) ? 0 : slotC + 1;
        slotP = (slotP == 2) ? 0 : slotP + 1;
    }

    const int g  = lane >> 2;
    const int tq = lane & 3;
    float* Cz = out + (size_t)z * CH * NPIX;
#pragma unroll
    for (int mt=0; mt<4; mt++) {
        const int row = cBase + warpM*64 + mt*16 + g;
#pragma unroll
        for (int nt=0; nt<4; nt++) {
            const int col = mBase + warpN*32 + nt*8 + tq*2;
            {
                const float2 xv = *reinterpret_cast<const float2*>(
                    &X[(size_t)row*NPIX + col]);
                float2 o;
                o.x = fmaf(gamma, acc[mt][nt][0], xv.x);
                o.y = fmaf(gamma, acc[mt][nt][1], xv.y);
                *reinterpret_cast<float2*>(&Cz[(size_t)row*NPIX + col]) = o;
            }
            {
                const float2 xv = *reinterpret_cast<const float2*>(
                    &X[(size_t)(row+8)*NPIX + col]);
                float2 o;
                o.x = fmaf(gamma, acc[mt][nt][2], xv.x);
                o.y = fmaf(gamma, acc[mt][nt][3], xv.y);
                *reinterpret_cast<float2*>(&Cz[(size_t)(row+8)*NPIX + col]) = o;
            }
        }
    }
}

// =====================================================================
extern "C" void kernel_launch(void* const* d_in, const int* in_sizes, int n_in,
                              void* d_out, int out_size)
{
    const float* x1     = (const float*)d_in[0];
    const float* x2     = (const float*)d_in[1];
    const float* f_w    = (const float*)d_in[2];
    const float* f_b    = (const float*)d_in[3];
    const float* g_w    = (const float*)d_in[4];
    const float* g_b    = (const float*)d_in[5];
    const float* h1_w   = (const float*)d_in[6];
    const float* h1_b   = (const float*)d_in[7];
    const float* h2_w   = (const float*)d_in[8];
    const float* h2_b   = (const float*)d_in[9];
    const float* gamma1 = (const float*)d_in[10];
    const float* gamma2 = (const float*)d_in[11];
    float* out = (float*)d_out;

    cudaFuncSetAttribute(fused_sm_kernel,
                         cudaFuncAttributeMaxDynamicSharedMemorySize, FSM_TOTAL);
    cudaFuncSetAttribute(proj_h_mma_kernel,
                         cudaFuncAttributeMaxDynamicSharedMemorySize, PH_SMEM);
    cudaFuncSetAttribute(out_mma_kernel,
                         cudaFuncAttributeMaxDynamicSharedMemorySize, OUT_SMEM);

    prep_kernel      <<<XT_BLKS + FG_BLKS + WC_BLKS, 256>>>(
        x1, x2, f_w, f_b, g_w, g_b, h1_w, h2_w);
    fused_sm_kernel  <<<dim3(64, NZ), 256, FSM_TOTAL>>>();
    proj_h_mma_kernel<<<dim3(32, 4, NZ), 128, PH_SMEM>>>(h1_b, h2_b);
    out_mma_kernel   <<<dim3(32, 2, NZ), 256, OUT_SMEM>>>(x1, x2, gamma1, gamma2, out);
}

// round 12
// speedup vs baseline: 1.1399x; 1.0910x over previous
#include <cuda_runtime.h>
#include <cuda_bf16.h>
#include <cstdint>
#include <math.h>

#define NBATCH 4
#define CH     256
#define NPIX   4096
#define KD     32
#define NZ     8   // 2 branches x 4 batches

// ---- scratch (module-load allocated; no runtime alloc) ----
__device__ __nv_bfloat16 g_fT[NZ][NPIX][KD];         // f^T : [n][k] bf16
__device__ __nv_bfloat16 g_gT[NZ][NPIX][KD];         // g^T : [m][k] bf16
__device__ float         g_invsum[NZ][NPIX];         // 1 / softmax row sum (shifted)
__device__ __nv_bfloat16 g_Xt[NZ][NPIX][CH];         // x^T : [n][c] bf16
__device__ __nv_bfloat16 g_Wb[2][CH][CH];            // h weights, bf16
__device__ __nv_bfloat16 g_Wfg[2*KD][CH];            // stacked [f_w; g_w], bf16
__device__ __nv_bfloat16 g_Hb[NZ][CH][NPIX];         // h projection (invsum-scaled), bf16
__device__ __nv_bfloat16 g_Pt[NZ][NPIX][NPIX];       // unnormalized P^T bf16: Pt[m][n]

__device__ __forceinline__ uint32_t smem_u32(const void* p) {
    uint32_t a;
    asm("{ .reg .u64 t; cvta.to.shared.u64 t, %1; cvt.u32.u64 %0, t; }" : "=r"(a) : "l"(p));
    return a;
}

__device__ __forceinline__ float ex2f(float x) {
    float r;
    asm("ex2.approx.f32 %0, %1;" : "=f"(r) : "f"(x));
    return r;
}

#define CP_ASYNC16(dst, src) \
    asm volatile("cp.async.cg.shared.global [%0], [%1], 16;" :: "r"(dst), "l"(src))
#define CP_ASYNC_COMMIT() asm volatile("cp.async.commit_group;" ::: "memory")
#define CP_ASYNC_WAIT_1() asm volatile("cp.async.wait_group 1;" ::: "memory")
#define CP_ASYNC_WAIT_0() asm volatile("cp.async.wait_group 0;" ::: "memory")

#define LDSM_X4(r0,r1,r2,r3,addr) \
    asm volatile("ldmatrix.sync.aligned.m8n8.x4.shared.b16 {%0,%1,%2,%3}, [%4];" \
        : "=r"(r0), "=r"(r1), "=r"(r2), "=r"(r3) : "r"(addr))

#define STSM_X2_TRANS(addr, r0, r1) \
    asm volatile("stmatrix.sync.aligned.m8n8.x2.trans.shared.b16 [%0], {%1, %2};" \
        :: "r"(addr), "r"(r0), "r"(r1) : "memory")

#define MMA_BF16(c0,c1,c2,c3,a0,a1,a2,a3,b0,b1) \
    asm volatile("mma.sync.aligned.m16n8k16.row.col.f32.bf16.bf16.f32 " \
        "{%0,%1,%2,%3}, {%4,%5,%6,%7}, {%8,%9}, {%0,%1,%2,%3};" \
        : "+f"(c0), "+f"(c1), "+f"(c2), "+f"(c3) \
        : "r"(a0), "r"(a1), "r"(a2), "r"(a3), "r"(b0), "r"(b1))

// =====================================================================
// Kernel P (merged prep): xt transpose (2048 blocks) + weight convert
// (32 blocks).  grid 2080, 256 threads.
// =====================================================================
#define XT_BLKS 2048
#define WC_BLKS 32

__global__ __launch_bounds__(256) void prep_kernel(
    const float* __restrict__ x1, const float* __restrict__ x2,
    const float* __restrict__ f_w, const float* __restrict__ g_w,
    const float* __restrict__ h1w, const float* __restrict__ h2w)
{
    const int bx = blockIdx.x;
    const int tid = threadIdx.x;

    if (bx < XT_BLKS) {
        // ---- xt: transpose x fp32 [c][n] -> Xt bf16 [n][c] ----
        const int z  = bx >> 8;
        const int ct = (bx >> 6) & 3;
        const int nt = bx & 63;
        const int br = z >> 2, b = z & 3;
        const float* X = (br ? x2 : x1) + (size_t)b * CH * NPIX;
        const int n0 = nt * 64;
        const int c0 = ct * 64;

        __shared__ unsigned short t[64][66];
        const int rr = tid >> 4;
        const int c4 = (tid & 15) * 4;

#pragma unroll
        for (int p=0;p<4;p++){
            const int crow = rr + p*16;
            const float4 v = *reinterpret_cast<const float4*>(
                &X[(size_t)(c0 + crow) * NPIX + n0 + c4]);
            t[crow][c4+0] = __bfloat16_as_ushort(__float2bfloat16(v.x));
            t[crow][c4+1] = __bfloat16_as_ushort(__float2bfloat16(v.y));
            t[crow][c4+2] = __bfloat16_as_ushort(__float2bfloat16(v.z));
            t[crow][c4+3] = __bfloat16_as_ushort(__float2bfloat16(v.w));
        }
        __syncthreads();

#pragma unroll
        for (int p=0;p<4;p++){
            const int nrow = rr + p*16;
            uint2 u;
            u.x = (uint32_t)t[c4+0][nrow] | ((uint32_t)t[c4+1][nrow] << 16);
            u.y = (uint32_t)t[c4+2][nrow] | ((uint32_t)t[c4+3][nrow] << 16);
            *reinterpret_cast<uint2*>(&g_Xt[z][n0 + nrow][c0 + c4]) = u;
        }
    } else {
        // ---- weight convert fp32 -> bf16 (h1w, h2w, f_w, g_w) ----
        const int blk = bx - XT_BLKS;
        const int idx = (blk * 256 + tid) * 8;
#pragma unroll
        for (int w = 0; w < 2; ++w) {
            const float* src = (w ? h2w : h1w) + idx;
            __nv_bfloat16* dst = &g_Wb[w][0][0] + idx;
#pragma unroll
            for (int j = 0; j < 2; ++j) {
                const float4 v = *reinterpret_cast<const float4*>(src + j*4);
                __nv_bfloat162 p0 = __float22bfloat162_rn(make_float2(v.x, v.y));
                __nv_bfloat162 p1 = __float22bfloat162_rn(make_float2(v.z, v.w));
                uint2 u;
                u.x = reinterpret_cast<uint32_t&>(p0);
                u.y = reinterpret_cast<uint32_t&>(p1);
                *reinterpret_cast<uint2*>(dst + j*4) = u;
            }
        }
        // f_w / g_w: 8192 elems each; 8192 threads total -> 1 elem each
        const int fgIdx = blk * 256 + tid;   // 0..8191
        g_Wfg[0][0*0] = g_Wfg[0][0];         // no-op keep compiler quiet
        if (fgIdx < KD * CH) {
            (&g_Wfg[0][0])[fgIdx]          = __float2bfloat16(f_w[fgIdx]);
            (&g_Wfg[KD][0])[fgIdx]         = __float2bfloat16(g_w[fgIdx]);
        }
    }
}

// =====================================================================
// Kernel 1: fused f/g projection via HMMA from g_Xt.
// A = g_Wfg [64 x 256] bf16 (rows 0-31 = f, 32-63 = g), B = Xt[n][c].
// CTA 64(k) x 128(n), 128 threads, 4 warps 64x32, K = 2 stages of 128.
// Epilogue: +bias, stmatrix.trans staging [n][64k], coalesced STG to
// g_fT[n][0..32) and g_gT[n][0..32).
// grid (32 n-tiles, NZ).
// =====================================================================
#define FG_LDA   136
#define FG_AST   (64*FG_LDA*2)               // 17408
#define FG_BST   (128*FG_LDA*2)              // 34816
#define FG_STG   (FG_AST + FG_BST)           // 52224
#define FG_SMEM  (2*FG_STG)                  // 104448 (staging reuses slot 0)

__global__ void __launch_bounds__(128, 2) proj_fg_mma_kernel(
    const float* __restrict__ f_b, const float* __restrict__ g_b)
{
    extern __shared__ char smf[];
    const uint32_t smBase = smem_u32(smf);

    const int tid = threadIdx.x;
    const int wid = tid >> 5, lane = tid & 31;
    const int z = blockIdx.y;
    const int nBase = blockIdx.x * 128;

    // loaders
    const int arow = tid >> 1;
    const int ahalf = (tid & 1) * 128;
    const char* gA = (const char*)&g_Wfg[arow][0] + ahalf;
    const uint32_t dA = (uint32_t)(arow * (FG_LDA*2) + ahalf);
    const char* gB = (const char*)&g_Xt[z][nBase + tid][0];
    const uint32_t dB = FG_AST + (uint32_t)(tid * (FG_LDA*2));

#pragma unroll
    for (int st = 0; st < 2; ++st) {
        const uint32_t slot = smBase + (uint32_t)st * FG_STG;
        const char* sa = gA + (size_t)st * 256;
        const char* sb = gB + (size_t)st * 256;
#pragma unroll
        for (int j=0;j<8;j++)  CP_ASYNC16(slot + dA + j*16, sa + j*16);
#pragma unroll
        for (int j=0;j<16;j++) CP_ASYNC16(slot + dB + j*16, sb + j*16);
        CP_ASYNC_COMMIT();
    }

    const int warpN = wid;
    const int lm  = lane & 15;
    const int aco = (lane >= 16) ? 8 : 0;
    uint32_t aOff[4];
#pragma unroll
    for (int mt=0; mt<4; mt++)
        aOff[mt] = (uint32_t)(((mt*16 + lm)*FG_LDA + aco)*2);
    const int bro = (lane & 7) + ((lane >= 16) ? 8 : 0);
    const int bco = (lane & 8) ? 8 : 0;
    uint32_t bOffA[2];
#pragma unroll
    for (int p=0; p<2; p++)
        bOffA[p] = FG_AST + (uint32_t)(((warpN*32 + p*16 + bro)*FG_LDA + bco)*2);

    float acc[4][4][4];
#pragma unroll
    for (int i=0;i<4;i++)
#pragma unroll
        for (int j=0;j<4;j++)
#pragma unroll
            for (int k=0;k<4;k++) acc[i][j][k] = 0.f;

#pragma unroll
    for (int st = 0; st < 2; ++st) {
        if (st == 0) CP_ASYNC_WAIT_1(); else CP_ASYNC_WAIT_0();
        __syncthreads();
        const uint32_t slot = smBase + (uint32_t)st * FG_STG;
#pragma unroll
        for (int ks = 0; ks < 8; ++ks) {
            uint32_t a[4][4];
#pragma unroll
            for (int mt=0; mt<4; mt++)
                LDSM_X4(a[mt][0], a[mt][1], a[mt][2], a[mt][3],
                        slot + aOff[mt] + ks*32);
            uint32_t bb[2][4];
#pragma unroll
            for (int p=0; p<2; p++)
                LDSM_X4(bb[p][0], bb[p][1], bb[p][2], bb[p][3],
                        slot + bOffA[p] + ks*32);
#pragma unroll
            for (int mt=0; mt<4; mt++)
#pragma unroll
                for (int nt=0; nt<4; nt++) {
                    const uint32_t b0 = bb[nt>>1][(nt&1)*2];
                    const uint32_t b1 = bb[nt>>1][(nt&1)*2+1];
                    MMA_BF16(acc[mt][nt][0], acc[mt][nt][1],
                             acc[mt][nt][2], acc[mt][nt][3],
                             a[mt][0], a[mt][1], a[mt][2], a[mt][3], b0, b1);
                }
        }
    }

    // ---- epilogue: +bias, stmatrix.trans into staging [128 n][72 k] ----
    __syncthreads();   // all LDSM done; reuse slot 0 as staging
    const int g  = lane >> 2;
    const uint32_t stLane = smBase +
        (uint32_t)(((lane & 7) * 72 + ((lane & 8) ? 8 : 0)) * 2);
#pragma unroll
    for (int mt=0; mt<4; mt++) {
        const int k0 = mt*16 + g;                 // 0..63
        const float* bp = (mt < 2) ? f_b : g_b;
        const float bv0 = bp[k0 & 31];
        const float bv8 = bp[(k0 + 8) & 31];
#pragma unroll
        for (int nt=0; nt<4; nt++) {
            __nv_bfloat162 q0 = __float22bfloat162_rn(
                make_float2(acc[mt][nt][0] + bv0, acc[mt][nt][1] + bv0));
            __nv_bfloat162 q1 = __float22bfloat162_rn(
                make_float2(acc[mt][nt][2] + bv8, acc[mt][nt][3] + bv8));
            const uint32_t addr = stLane +
                (uint32_t)(((warpN*32 + nt*8)*72 + mt*16) * 2);
            STSM_X2_TRANS(addr,
                          reinterpret_cast<uint32_t&>(q0),
                          reinterpret_cast<uint32_t&>(q1));
        }
    }
    __syncthreads();

    // coalesced global store: thread t -> n row t; f = cols 0-31, g = 32-63
    {
        const char* row = smf + (size_t)tid * 144;
        uint4* fDst = reinterpret_cast<uint4*>(&g_fT[z][nBase + tid][0]);
        uint4* gDst = reinterpret_cast<uint4*>(&g_gT[z][nBase + tid][0]);
#pragma unroll
        for (int j=0;j<4;j++)
            fDst[j] = *reinterpret_cast<const uint4*>(row + j*16);
#pragma unroll
        for (int j=0;j<4;j++)
            gDst[j] = *reinterpret_cast<const uint4*>(row + 64 + j*16);
    }
}

// =====================================================================
// Kernel 2 (fused, single pass): scores (HMMA bf16) + fixed-shift exp +
// stmatrix.trans transposed bf16 P' staging + shifted row sums.
// =====================================================================
#define FLD   40
#define FSM_FT   0u
#define FSM_G    5120u
#define FSM_GSZ  20480u
#define FSM_ST   46080u
#define FSM_RED  82944u
#define FSM_TOTAL 83968u

__global__ __launch_bounds__(256) void fused_sm_kernel()
{
    extern __shared__ __align__(16) char sm[];
    const uint32_t smBase = smem_u32(sm);
    float* red = reinterpret_cast<float*>(sm + FSM_RED);

    const int tid  = threadIdx.x;
    const int lane = tid & 31, wid = tid >> 5;
    const int z  = blockIdx.y;
    const int n0 = blockIdx.x * 64;
    const int warpM = wid >> 2;
    const int warpN = wid & 3;
    const int qg = lane >> 2, tq = lane & 3;

    {
        const int row = tid >> 2, ch = tid & 3;
        CP_ASYNC16(smBase + FSM_FT + (uint32_t)((row*FLD + ch*8)*2),
                   (const char*)&g_fT[z][n0 + row][ch*8]);
    }
    CP_ASYNC_COMMIT();

    const int lm  = lane & 15;
    const int aco = (lane >= 16) ? 8 : 0;
    uint32_t aAddr[2];
#pragma unroll
    for (int mt=0; mt<2; mt++)
        aAddr[mt] = smBase + FSM_FT +
            (uint32_t)(((warpM*32 + mt*16 + lm)*FLD + aco)*2);
    const int bro = (lane & 7) + ((lane >= 16) ? 8 : 0);
    const int bco = (lane & 8) ? 8 : 0;
    uint32_t bOff[4];
#pragma unroll
    for (int p=0; p<4; p++)
        bOff[p] = (uint32_t)(((warpN*64 + p*16 + bro)*FLD + bco)*2);

    const int grow = tid >> 2, gch = tid & 3;

    const uint32_t stLane = smBase + FSM_ST +
        (uint32_t)(((lane & 7) * 72 + ((lane & 8) ? 8 : 0)) * 2);

    float rsum[4];
#pragma unroll
    for (int i=0;i<4;i++) rsum[i] = 0.f;

    const float CEXP  = 0.17677669529663688f * 1.4426950408889634f;
    const float SHIFT = 16.0f * 1.4426950408889634f;

    {
        const char* src = (const char*)&g_gT[z][0][0];
#pragma unroll
        for (int i=0;i<4;i++)
            CP_ASYNC16(smBase + FSM_G + (uint32_t)(((grow+i*64)*FLD + gch*8)*2),
                       src + (size_t)(grow + i*64)*64 + gch*16);
        CP_ASYNC_COMMIT();
    }
    for (int t = 0; t < 16; ++t) {
        if (t < 15) {
            const uint32_t dst = smBase + FSM_G + (uint32_t)((t+1)&1)*FSM_GSZ;
            const char* src = (const char*)&g_gT[z][(t+1)*256][0];
#pragma unroll
            for (int i=0;i<4;i++)
                CP_ASYNC16(dst + (uint32_t)(((grow+i*64)*FLD + gch*8)*2),
                           src + (size_t)(grow + i*64)*64 + gch*16);
            CP_ASYNC_COMMIT();
            CP_ASYNC_WAIT_1();
        } else {
            CP_ASYNC_WAIT_0();
        }
        __syncthreads();

        const uint32_t gb = smBase + FSM_G + (uint32_t)(t&1)*FSM_GSZ;
        float acc[2][8][4];
#pragma unroll
        for (int mt=0;mt<2;mt++)
#pragma unroll
            for (int nt=0;nt<8;nt++)
#pragma unroll
                for (int c=0;c<4;c++) acc[mt][nt][c] = 0.f;

#pragma unroll
        for (int ks = 0; ks < 2; ++ks) {
            uint32_t a[2][4];
#pragma unroll
            for (int mt=0; mt<2; mt++)
                LDSM_X4(a[mt][0], a[mt][1], a[mt][2], a[mt][3],
                        aAddr[mt] + ks*32);
            uint32_t bb[4][4];
#pragma unroll
            for (int p=0; p<4; p++)
                LDSM_X4(bb[p][0], bb[p][1], bb[p][2], bb[p][3],
                        gb + bOff[p] + ks*32);
#pragma unroll
            for (int mt=0; mt<2; mt++)
#pragma unroll
                for (int nt=0; nt<8; nt++) {
                    const uint32_t b0 = bb[nt>>1][(nt&1)*2];
                    const uint32_t b1 = bb[nt>>1][(nt&1)*2+1];
                    MMA_BF16(acc[mt][nt][0], acc[mt][nt][1],
                             acc[mt][nt][2], acc[mt][nt][3],
                             a[mt][0], a[mt][1], a[mt][2], a[mt][3], b0, b1);
                }
        }

        {
#pragma unroll
            for (int mt=0;mt<2;mt++)
#pragma unroll
                for (int nt=0;nt<8;nt++){
                    const float p0 = ex2f(fmaf(acc[mt][nt][0], CEXP, -SHIFT));
                    const float p1 = ex2f(fmaf(acc[mt][nt][1], CEXP, -SHIFT));
                    const float p2 = ex2f(fmaf(acc[mt][nt][2], CEXP, -SHIFT));
                    const float p3 = ex2f(fmaf(acc[mt][nt][3], CEXP, -SHIFT));
                    rsum[mt*2+0] += p0 + p1;
                    rsum[mt*2+1] += p2 + p3;
                    __nv_bfloat162 q0 = __float22bfloat162_rn(make_float2(p0, p1));
                    __nv_bfloat162 q1 = __float22bfloat162_rn(make_float2(p2, p3));
                    const uint32_t addr = stLane +
                        (uint32_t)(((warpN*64 + nt*8)*72 + warpM*32 + mt*16) * 2);
                    STSM_X2_TRANS(addr,
                                  reinterpret_cast<uint32_t&>(q0),
                                  reinterpret_cast<uint32_t&>(q1));
                }
            __syncthreads();
            const int ch = tid & 7;
#pragma unroll
            for (int i=0;i<8;i++){
                const int ml = (tid>>3) + i*32;
                const uint4 v = *reinterpret_cast<const uint4*>(
                    sm + FSM_ST + (uint32_t)((ml*72 + ch*8)*2));
                *reinterpret_cast<uint4*>(&g_Pt[z][t*256 + ml][n0 + ch*8]) = v;
            }
            __syncthreads();
        }
    }

#pragma unroll
    for (int i=0;i<4;i++){
        float v = rsum[i];
        v += __shfl_xor_sync(0xffffffffu, v, 1);
        v += __shfl_xor_sync(0xffffffffu, v, 2);
        rsum[i] = v;
    }
    if (tq == 0) {
#pragma unroll
        for (int i=0;i<4;i++){
            const int r = warpM*32 + (i>>1)*16 + qg + (i&1)*8;
            red[r*4 + warpN] = rsum[i];
        }
    }
    __syncthreads();
    if (warpN == 0 && tq == 0) {
#pragma unroll
        for (int i=0;i<4;i++){
            const int r = warpM*32 + (i>>1)*16 + qg + (i&1)*8;
            const float s = red[r*4+0] + red[r*4+1] + red[r*4+2] + red[r*4+3];
            g_invsum[z][n0 + r] = 1.0f / s;
        }
    }
}

// =====================================================================
// Kernel 3: h projection via HMMA, fully cp.async + K pipelined.
// CTA 64(o) x 128(n), 128 threads, 4 warps 64x32, K = 2 stages of 128.
// =====================================================================
#define PH_LDA   136
#define PH_AST   (64*PH_LDA*2)
#define PH_BST   (128*PH_LDA*2)
#define PH_STG   (PH_AST + PH_BST)
#define PH_SMEM  (2*PH_STG)

__global__ void __launch_bounds__(128, 2) proj_h_mma_kernel(
    const float* __restrict__ h1b, const float* __restrict__ h2b)
{
    extern __shared__ char smh[];
    const uint32_t smBase = smem_u32(smh);

    const int tid = threadIdx.x;
    const int wid = tid >> 5, lane = tid & 31;
    const int z = blockIdx.z, br = z >> 2;
    const int nBase = blockIdx.x * 128;
    const int oBase = blockIdx.y * 64;
    const float* bias = br ? h2b : h1b;

    const int arow = tid >> 1;
    const int ahalf = (tid & 1) * 128;
    const char* gA = (const char*)&g_Wb[br][oBase + arow][0] + ahalf;
    const uint32_t dA = (uint32_t)(arow * (PH_LDA*2) + ahalf);
    const char* gB = (const char*)&g_Xt[z][nBase + tid][0];
    const uint32_t dB = PH_AST + (uint32_t)(tid * (PH_LDA*2));

#pragma unroll
    for (int st = 0; st < 2; ++st) {
        const uint32_t slot = smBase + (uint32_t)st * PH_STG;
        const char* sa = gA + (size_t)st * 256;
        const char* sb = gB + (size_t)st * 256;
#pragma unroll
        for (int j=0;j<8;j++)  CP_ASYNC16(slot + dA + j*16, sa + j*16);
#pragma unroll
        for (int j=0;j<16;j++) CP_ASYNC16(slot + dB + j*16, sb + j*16);
        CP_ASYNC_COMMIT();
    }

    const int warpN = wid;
    const int lm  = lane & 15;
    const int aco = (lane >= 16) ? 8 : 0;
    uint32_t aOff[4];
#pragma unroll
    for (int mt=0; mt<4; mt++)
        aOff[mt] = (uint32_t)(((mt*16 + lm)*PH_LDA + aco)*2);
    const int bro = (lane & 7) + ((lane >= 16) ? 8 : 0);
    const int bco = (lane & 8) ? 8 : 0;
    uint32_t bOffA[2];
#pragma unroll
    for (int p=0; p<2; p++)
        bOffA[p] = PH_AST + (uint32_t)(((warpN*32 + p*16 + bro)*PH_LDA + bco)*2);

    float acc[4][4][4];
#pragma unroll
    for (int i=0;i<4;i++)
#pragma unroll
        for (int j=0;j<4;j++)
#pragma unroll
            for (int k=0;k<4;k++) acc[i][j][k] = 0.f;

#pragma unroll
    for (int st = 0; st < 2; ++st) {
        if (st == 0) CP_ASYNC_WAIT_1(); else CP_ASYNC_WAIT_0();
        __syncthreads();
        const uint32_t slot = smBase + (uint32_t)st * PH_STG;
#pragma unroll
        for (int ks = 0; ks < 8; ++ks) {
            uint32_t a[4][4];
#pragma unroll
            for (int mt=0; mt<4; mt++)
                LDSM_X4(a[mt][0], a[mt][1], a[mt][2], a[mt][3],
                        slot + aOff[mt] + ks*32);
            uint32_t bb[2][4];
#pragma unroll
            for (int p=0; p<2; p++)
                LDSM_X4(bb[p][0], bb[p][1], bb[p][2], bb[p][3],
                        slot + bOffA[p] + ks*32);
#pragma unroll
            for (int mt=0; mt<4; mt++)
#pragma unroll
                for (int nt=0; nt<4; nt++) {
                    const uint32_t b0 = bb[nt>>1][(nt&1)*2];
                    const uint32_t b1 = bb[nt>>1][(nt&1)*2+1];
                    MMA_BF16(acc[mt][nt][0], acc[mt][nt][1],
                             acc[mt][nt][2], acc[mt][nt][3],
                             a[mt][0], a[mt][1], a[mt][2], a[mt][3], b0, b1);
                }
        }
    }

    const int g  = lane >> 2;
    const int tq = lane & 3;
#pragma unroll
    for (int mt=0; mt<4; mt++) {
        const int row0 = oBase + mt*16 + g;
        const float bv0 = bias[row0];
        const float bv8 = bias[row0 + 8];
#pragma unroll
        for (int nt=0; nt<4; nt++) {
            const int col = nBase + warpN*32 + nt*8 + tq*2;
            const float2 iv = *reinterpret_cast<const float2*>(&g_invsum[z][col]);
            {
                const float v0 = (acc[mt][nt][0] + bv0) * iv.x;
                const float v1 = (acc[mt][nt][1] + bv0) * iv.y;
                __nv_bfloat162 pk = __float22bfloat162_rn(make_float2(v0, v1));
                *reinterpret_cast<uint32_t*>(&g_Hb[z][row0][col]) =
                    reinterpret_cast<uint32_t&>(pk);
            }
            {
                const float v0 = (acc[mt][nt][2] + bv8) * iv.x;
                const float v1 = (acc[mt][nt][3] + bv8) * iv.y;
                __nv_bfloat162 pk = __float22bfloat162_rn(make_float2(v0, v1));
                *reinterpret_cast<uint32_t*>(&g_Hb[z][row0 + 8][col]) =
                    reinterpret_cast<uint32_t&>(pk);
            }
        }
    }
}

// =====================================================================
// Kernel 4: out[z] = gamma * (H' @ P') + x  via mma.sync bf16 (HMMA).
// Round-5 proven config (frozen).
// =====================================================================
#define BK      64
#define LDSS    72
#define STGB    (128*LDSS*2)
#define NSTG    3
#define OUT_SMEM (NSTG*2*STGB)

__global__ void __launch_bounds__(256, 2) out_mma_kernel(
    const float* __restrict__ x1, const float* __restrict__ x2,
    const float* __restrict__ gamma1, const float* __restrict__ gamma2,
    float* __restrict__ out)
{
    extern __shared__ char smo[];
    const uint32_t smBase = smem_u32(smo);

    const int tid = threadIdx.x;
    const int wid = tid >> 5, lane = tid & 31;
    const int z = blockIdx.z, br = z >> 2, b = z & 3;
    const int mBase = blockIdx.x * 128;
    const int cBase = blockIdx.y * 128;
    const float* X = (br ? x2 : x1) + (size_t)b * CH * NPIX;
    const float gamma = (br ? gamma2 : gamma1)[0];

    const int lrow = tid >> 1;
    const int lcol = (tid & 1) * 32;
    const char* gAp = (const char*)(&g_Hb[z][cBase + lrow][lcol]);
    const char* gBp = (const char*)(&g_Pt[z][mBase + lrow][lcol]);
    const uint32_t ldOff = (uint32_t)((lrow*LDSS + lcol)*2);

    const int warpM = wid >> 2;
    const int warpN = wid & 3;
    const int lm  = lane & 15;
    const int aco = (lane >= 16) ? 8 : 0;
    uint32_t aOff[4];
#pragma unroll
    for (int mt=0; mt<4; mt++)
        aOff[mt] = (uint32_t)(((warpM*64 + mt*16 + lm)*LDSS + aco)*2);
    const int bro = (lane & 7) + ((lane >= 16) ? 8 : 0);
    const int bco = (lane & 8) ? 8 : 0;
    uint32_t bOff[2];
#pragma unroll
    for (int p=0; p<2; p++)
        bOff[p] = (uint32_t)(((warpN*32 + p*16 + bro)*LDSS + bco)*2) + STGB;

    float acc[4][4][4];
#pragma unroll
    for (int i=0;i<4;i++)
#pragma unroll
        for (int j=0;j<4;j++)
#pragma unroll
            for (int k=0;k<4;k++) acc[i][j][k] = 0.f;

#pragma unroll
    for (int st=0; st<2; ++st) {
        const uint32_t slot = smBase + (uint32_t)st * (2*STGB);
        const char* sa = gAp + (size_t)st * (BK*2);
        const char* sb = gBp + (size_t)st * (BK*2);
#pragma unroll
        for (int j=0;j<4;j++) CP_ASYNC16(slot + ldOff + j*16, sa + j*16);
#pragma unroll
        for (int j=0;j<4;j++) CP_ASYNC16(slot + STGB + ldOff + j*16, sb + j*16);
        CP_ASYNC_COMMIT();
    }

    int slotC = 0;
    int slotP = 2;
    for (int it = 0; it < NPIX/BK; ++it) {
        CP_ASYNC_WAIT_1();
        __syncthreads();

        if (it + 2 < NPIX/BK) {
            const uint32_t slot = smBase + (uint32_t)slotP * (2*STGB);
            const char* sa = gAp + (size_t)(it+2) * (BK*2);
            const char* sb = gBp + (size_t)(it+2) * (BK*2);
#pragma unroll
            for (int j=0;j<4;j++) CP_ASYNC16(slot + ldOff + j*16, sa + j*16);
#pragma unroll
            for (int j=0;j<4;j++) CP_ASYNC16(slot + STGB + ldOff + j*16, sb + j*16);
        }
        CP_ASYNC_COMMIT();

        const uint32_t sb = smBase + (uint32_t)slotC * (2*STGB);
#pragma unroll
        for (int ks = 0; ks < 4; ++ks) {
            uint32_t a[4][4];
#pragma unroll
            for (int mt=0; mt<4; mt++)
                LDSM_X4(a[mt][0], a[mt][1], a[mt][2], a[mt][3],
                        sb + aOff[mt] + ks*32);
            uint32_t bb[2][4];
#pragma unroll
            for (int p=0; p<2; p++)
                LDSM_X4(bb[p][0], bb[p][1], bb[p][2], bb[p][3],
                        sb + bOff[p] + ks*32);
#pragma unroll
            for (int mt=0; mt<4; mt++)
#pragma unroll
                for (int nt=0; nt<4; nt++) {
                    const uint32_t b0 = bb[nt>>1][(nt&1)*2];
                    const uint32_t b1 = bb[nt>>1][(nt&1)*2+1];
                    MMA_BF16(acc[mt][nt][0], acc[mt][nt][1],
                             acc[mt][nt][2], acc[mt][nt][3],
                             a[mt][0], a[mt][1], a[mt][2], a[mt][3], b0, b1);
                }
        }

        slotC = (slotC == 2) ? 0 : slotC + 1;
        slotP = (slotP == 2) ? 0 : slotP + 1;
    }

    const int g  = lane >> 2;
    const int tq = lane & 3;
    float* Cz = out + (size_t)z * CH * NPIX;
#pragma unroll
    for (int mt=0; mt<4; mt++) {
        const int row = cBase + warpM*64 + mt*16 + g;
#pragma unroll
        for (int nt=0; nt<4; nt++) {
            const int col = mBase + warpN*32 + nt*8 + tq*2;
            {
                const float2 xv = *reinterpret_cast<const float2*>(
                    &X[(size_t)row*NPIX + col]);
                float2 o;
                o.x = fmaf(gamma, acc[mt][nt][0], xv.x);
                o.y = fmaf(gamma, acc[mt][nt][1], xv.y);
                *reinterpret_cast<float2*>(&Cz[(size_t)row*NPIX + col]) = o;
            }
            {
                const float2 xv = *reinterpret_cast<const float2*>(
                    &X[(size_t)(row+8)*NPIX + col]);
                float2 o;
                o.x = fmaf(gamma, acc[mt][nt][2], xv.x);
                o.y = fmaf(gamma, acc[mt][nt][3], xv.y);
                *reinterpret_cast<float2*>(&Cz[(size_t)(row+8)*NPIX + col]) = o;
            }
        }
    }
}

// =====================================================================
extern "C" void kernel_launch(void* const* d_in, const int* in_sizes, int n_in,
                              void* d_out, int out_size)
{
    const float* x1     = (const float*)d_in[0];
    const float* x2     = (const float*)d_in[1];
    const float* f_w    = (const float*)d_in[2];
    const float* f_b    = (const float*)d_in[3];
    const float* g_w    = (const float*)d_in[4];
    const float* g_b    = (const float*)d_in[5];
    const float* h1_w   = (const float*)d_in[6];
    const float* h1_b   = (const float*)d_in[7];
    const float* h2_w   = (const float*)d_in[8];
    const float* h2_b   = (const float*)d_in[9];
    const float* gamma1 = (const float*)d_in[10];
    const float* gamma2 = (const float*)d_in[11];
    float* out = (float*)d_out;

    cudaFuncSetAttribute(proj_fg_mma_kernel,
                         cudaFuncAttributeMaxDynamicSharedMemorySize, FG_SMEM);
    cudaFuncSetAttribute(fused_sm_kernel,
                         cudaFuncAttributeMaxDynamicSharedMemorySize, FSM_TOTAL);
    cudaFuncSetAttribute(proj_h_mma_kernel,
                         cudaFuncAttributeMaxDynamicSharedMemorySize, PH_SMEM);
    cudaFuncSetAttribute(out_mma_kernel,
                         cudaFuncAttributeMaxDynamicSharedMemorySize, OUT_SMEM);

    prep_kernel       <<<XT_BLKS + WC_BLKS, 256>>>(
        x1, x2, f_w, g_w, h1_w, h2_w);
    proj_fg_mma_kernel<<<dim3(32, NZ), 128, FG_SMEM>>>(f_b, g_b);
    fused_sm_kernel   <<<dim3(64, NZ), 256, FSM_TOTAL>>>();
    proj_h_mma_kernel <<<dim3(32, 4, NZ), 128, PH_SMEM>>>(h1_b, h2_b);
    out_mma_kernel    <<<dim3(32, 2, NZ), 256, OUT_SMEM>>>(x1, x2, gamma1, gamma2, out);
}

// round 13
// speedup vs baseline: 1.1426x; 1.0024x over previous
#include <cuda_runtime.h>
#include <cuda_bf16.h>
#include <cstdint>
#include <math.h>

#define NBATCH 4
#define CH     256
#define NPIX   4096
#define KD     32
#define NZ     8   // 2 branches x 4 batches

// ---- scratch (module-load allocated; no runtime alloc) ----
__device__ __nv_bfloat16 g_fT[NZ][NPIX][KD];         // f^T : [n][k] bf16
__device__ __nv_bfloat16 g_gT[NZ][NPIX][KD];         // g^T : [m][k] bf16
__device__ float         g_invsum[NZ][NPIX];         // 1 / softmax row sum (shifted)
__device__ __nv_bfloat16 g_Xt[NZ][NPIX][CH];         // x^T : [n][c] bf16
__device__ __nv_bfloat16 g_Wb[2][CH][CH];            // h weights, bf16
__device__ __nv_bfloat16 g_Wfg[2*KD][CH];            // stacked [f_w; g_w], bf16
__device__ __nv_bfloat16 g_Hb[NZ][CH][NPIX];         // h projection (invsum-scaled), bf16
__device__ __nv_bfloat16 g_Pt[NZ][NPIX][NPIX];       // unnormalized P^T bf16: Pt[m][n]

// dynamic tile counters (reset by prep each launch)
__device__ unsigned int g_ctr_out;
__device__ unsigned int g_ctr_sm;
__device__ unsigned int g_ctr_ph;

__device__ __forceinline__ uint32_t smem_u32(const void* p) {
    uint32_t a;
    asm("{ .reg .u64 t; cvta.to.shared.u64 t, %1; cvt.u32.u64 %0, t; }" : "=r"(a) : "l"(p));
    return a;
}

__device__ __forceinline__ float ex2f(float x) {
    float r;
    asm("ex2.approx.f32 %0, %1;" : "=f"(r) : "f"(x));
    return r;
}

#define CP_ASYNC16(dst, src) \
    asm volatile("cp.async.cg.shared.global [%0], [%1], 16;" :: "r"(dst), "l"(src))
#define CP_ASYNC_COMMIT() asm volatile("cp.async.commit_group;" ::: "memory")
#define CP_ASYNC_WAIT_1() asm volatile("cp.async.wait_group 1;" ::: "memory")
#define CP_ASYNC_WAIT_0() asm volatile("cp.async.wait_group 0;" ::: "memory")

#define LDSM_X4(r0,r1,r2,r3,addr) \
    asm volatile("ldmatrix.sync.aligned.m8n8.x4.shared.b16 {%0,%1,%2,%3}, [%4];" \
        : "=r"(r0), "=r"(r1), "=r"(r2), "=r"(r3) : "r"(addr))

#define STSM_X2_TRANS(addr, r0, r1) \
    asm volatile("stmatrix.sync.aligned.m8n8.x2.trans.shared.b16 [%0], {%1, %2};" \
        :: "r"(addr), "r"(r0), "r"(r1) : "memory")

#define MMA_BF16(c0,c1,c2,c3,a0,a1,a2,a3,b0,b1) \
    asm volatile("mma.sync.aligned.m16n8k16.row.col.f32.bf16.bf16.f32 " \
        "{%0,%1,%2,%3}, {%4,%5,%6,%7}, {%8,%9}, {%0,%1,%2,%3};" \
        : "+f"(c0), "+f"(c1), "+f"(c2), "+f"(c3) \
        : "r"(a0), "r"(a1), "r"(a2), "r"(a3), "r"(b0), "r"(b1))

// =====================================================================
// Kernel P (merged prep): xt transpose (2048 blocks) + weight convert
// (32 blocks) + counter reset.
// =====================================================================
#define XT_BLKS 2048
#define WC_BLKS 32

__global__ __launch_bounds__(256) void prep_kernel(
    const float* __restrict__ x1, const float* __restrict__ x2,
    const float* __restrict__ f_w, const float* __restrict__ g_w,
    const float* __restrict__ h1w, const float* __restrict__ h2w)
{
    const int bx = blockIdx.x;
    const int tid = threadIdx.x;

    if (bx < XT_BLKS) {
        const int z  = bx >> 8;
        const int ct = (bx >> 6) & 3;
        const int nt = bx & 63;
        const int br = z >> 2, b = z & 3;
        const float* X = (br ? x2 : x1) + (size_t)b * CH * NPIX;
        const int n0 = nt * 64;
        const int c0 = ct * 64;

        __shared__ unsigned short t[64][66];
        const int rr = tid >> 4;
        const int c4 = (tid & 15) * 4;

#pragma unroll
        for (int p=0;p<4;p++){
            const int crow = rr + p*16;
            const float4 v = *reinterpret_cast<const float4*>(
                &X[(size_t)(c0 + crow) * NPIX + n0 + c4]);
            t[crow][c4+0] = __bfloat16_as_ushort(__float2bfloat16(v.x));
            t[crow][c4+1] = __bfloat16_as_ushort(__float2bfloat16(v.y));
            t[crow][c4+2] = __bfloat16_as_ushort(__float2bfloat16(v.z));
            t[crow][c4+3] = __bfloat16_as_ushort(__float2bfloat16(v.w));
        }
        __syncthreads();

#pragma unroll
        for (int p=0;p<4;p++){
            const int nrow = rr + p*16;
            uint2 u;
            u.x = (uint32_t)t[c4+0][nrow] | ((uint32_t)t[c4+1][nrow] << 16);
            u.y = (uint32_t)t[c4+2][nrow] | ((uint32_t)t[c4+3][nrow] << 16);
            *reinterpret_cast<uint2*>(&g_Xt[z][n0 + nrow][c0 + c4]) = u;
        }
    } else {
        const int blk = bx - XT_BLKS;
        if (blk == 0 && tid == 0) {
            g_ctr_out = 0; g_ctr_sm = 0; g_ctr_ph = 0;
        }
        const int idx = (blk * 256 + tid) * 8;
#pragma unroll
        for (int w = 0; w < 2; ++w) {
            const float* src = (w ? h2w : h1w) + idx;
            __nv_bfloat16* dst = &g_Wb[w][0][0] + idx;
#pragma unroll
            for (int j = 0; j < 2; ++j) {
                const float4 v = *reinterpret_cast<const float4*>(src + j*4);
                __nv_bfloat162 p0 = __float22bfloat162_rn(make_float2(v.x, v.y));
                __nv_bfloat162 p1 = __float22bfloat162_rn(make_float2(v.z, v.w));
                uint2 u;
                u.x = reinterpret_cast<uint32_t&>(p0);
                u.y = reinterpret_cast<uint32_t&>(p1);
                *reinterpret_cast<uint2*>(dst + j*4) = u;
            }
        }
        const int fgIdx = blk * 256 + tid;   // 0..8191
        if (fgIdx < KD * CH) {
            (&g_Wfg[0][0])[fgIdx]  = __float2bfloat16(f_w[fgIdx]);
            (&g_Wfg[KD][0])[fgIdx] = __float2bfloat16(g_w[fgIdx]);
        }
    }
}

// =====================================================================
// Kernel 1: fused f/g projection via HMMA from g_Xt.  (unchanged;
// grid 256 CTAs already fits one wave)
// =====================================================================
#define FG_LDA   136
#define FG_AST   (64*FG_LDA*2)
#define FG_BST   (128*FG_LDA*2)
#define FG_STG   (FG_AST + FG_BST)
#define FG_SMEM  (2*FG_STG)

__global__ void __launch_bounds__(128, 2) proj_fg_mma_kernel(
    const float* __restrict__ f_b, const float* __restrict__ g_b)
{
    extern __shared__ char smf[];
    const uint32_t smBase = smem_u32(smf);

    const int tid = threadIdx.x;
    const int wid = tid >> 5, lane = tid & 31;
    const int z = blockIdx.y;
    const int nBase = blockIdx.x * 128;

    const int arow = tid >> 1;
    const int ahalf = (tid & 1) * 128;
    const char* gA = (const char*)&g_Wfg[arow][0] + ahalf;
    const uint32_t dA = (uint32_t)(arow * (FG_LDA*2) + ahalf);
    const char* gB = (const char*)&g_Xt[z][nBase + tid][0];
    const uint32_t dB = FG_AST + (uint32_t)(tid * (FG_LDA*2));

#pragma unroll
    for (int st = 0; st < 2; ++st) {
        const uint32_t slot = smBase + (uint32_t)st * FG_STG;
        const char* sa = gA + (size_t)st * 256;
        const char* sb = gB + (size_t)st * 256;
#pragma unroll
        for (int j=0;j<8;j++)  CP_ASYNC16(slot + dA + j*16, sa + j*16);
#pragma unroll
        for (int j=0;j<16;j++) CP_ASYNC16(slot + dB + j*16, sb + j*16);
        CP_ASYNC_COMMIT();
    }

    const int warpN = wid;
    const int lm  = lane & 15;
    const int aco = (lane >= 16) ? 8 : 0;
    uint32_t aOff[4];
#pragma unroll
    for (int mt=0; mt<4; mt++)
        aOff[mt] = (uint32_t)(((mt*16 + lm)*FG_LDA + aco)*2);
    const int bro = (lane & 7) + ((lane >= 16) ? 8 : 0);
    const int bco = (lane & 8) ? 8 : 0;
    uint32_t bOffA[2];
#pragma unroll
    for (int p=0; p<2; p++)
        bOffA[p] = FG_AST + (uint32_t)(((warpN*32 + p*16 + bro)*FG_LDA + bco)*2);

    float acc[4][4][4];
#pragma unroll
    for (int i=0;i<4;i++)
#pragma unroll
        for (int j=0;j<4;j++)
#pragma unroll
            for (int k=0;k<4;k++) acc[i][j][k] = 0.f;

#pragma unroll
    for (int st = 0; st < 2; ++st) {
        if (st == 0) CP_ASYNC_WAIT_1(); else CP_ASYNC_WAIT_0();
        __syncthreads();
        const uint32_t slot = smBase + (uint32_t)st * FG_STG;
#pragma unroll
        for (int ks = 0; ks < 8; ++ks) {
            uint32_t a[4][4];
#pragma unroll
            for (int mt=0; mt<4; mt++)
                LDSM_X4(a[mt][0], a[mt][1], a[mt][2], a[mt][3],
                        slot + aOff[mt] + ks*32);
            uint32_t bb[2][4];
#pragma unroll
            for (int p=0; p<2; p++)
                LDSM_X4(bb[p][0], bb[p][1], bb[p][2], bb[p][3],
                        slot + bOffA[p] + ks*32);
#pragma unroll
            for (int mt=0; mt<4; mt++)
#pragma unroll
                for (int nt=0; nt<4; nt++) {
                    const uint32_t b0 = bb[nt>>1][(nt&1)*2];
                    const uint32_t b1 = bb[nt>>1][(nt&1)*2+1];
                    MMA_BF16(acc[mt][nt][0], acc[mt][nt][1],
                             acc[mt][nt][2], acc[mt][nt][3],
                             a[mt][0], a[mt][1], a[mt][2], a[mt][3], b0, b1);
                }
        }
    }

    __syncthreads();
    const int g  = lane >> 2;
    const uint32_t stLane = smBase +
        (uint32_t)(((lane & 7) * 72 + ((lane & 8) ? 8 : 0)) * 2);
#pragma unroll
    for (int mt=0; mt<4; mt++) {
        const int k0 = mt*16 + g;
        const float* bp = (mt < 2) ? f_b : g_b;
        const float bv0 = bp[k0 & 31];
        const float bv8 = bp[(k0 + 8) & 31];
#pragma unroll
        for (int nt=0; nt<4; nt++) {
            __nv_bfloat162 q0 = __float22bfloat162_rn(
                make_float2(acc[mt][nt][0] + bv0, acc[mt][nt][1] + bv0));
            __nv_bfloat162 q1 = __float22bfloat162_rn(
                make_float2(acc[mt][nt][2] + bv8, acc[mt][nt][3] + bv8));
            const uint32_t addr = stLane +
                (uint32_t)(((warpN*32 + nt*8)*72 + mt*16) * 2);
            STSM_X2_TRANS(addr,
                          reinterpret_cast<uint32_t&>(q0),
                          reinterpret_cast<uint32_t&>(q1));
        }
    }
    __syncthreads();

    {
        const char* row = smf + (size_t)tid * 144;
        uint4* fDst = reinterpret_cast<uint4*>(&g_fT[z][nBase + tid][0]);
        uint4* gDst = reinterpret_cast<uint4*>(&g_gT[z][nBase + tid][0]);
#pragma unroll
        for (int j=0;j<4;j++)
            fDst[j] = *reinterpret_cast<const uint4*>(row + j*16);
#pragma unroll
        for (int j=0;j<4;j++)
            gDst[j] = *reinterpret_cast<const uint4*>(row + 64 + j*16);
    }
}

// =====================================================================
// Kernel 2 (fused, single pass, dynamic tiles): scores + exp + stmatrix
// staging + Pt write + invsum.  512 tiles.
// =====================================================================
#define FLD   40
#define FSM_FT   0u
#define FSM_G    5120u
#define FSM_GSZ  20480u
#define FSM_ST   46080u
#define FSM_RED  82944u
#define FSM_TOTAL 83968u
#define SM_TILES 512

__global__ __launch_bounds__(256) void fused_sm_kernel()
{
    extern __shared__ __align__(16) char sm[];
    __shared__ unsigned int s_tile;
    const uint32_t smBase = smem_u32(sm);
    float* red = reinterpret_cast<float*>(sm + FSM_RED);

    const int tid  = threadIdx.x;
    const int lane = tid & 31, wid = tid >> 5;
    const int warpM = wid >> 2;
    const int warpN = wid & 3;
    const int qg = lane >> 2, tq = lane & 3;

    const int lm  = lane & 15;
    const int aco = (lane >= 16) ? 8 : 0;
    uint32_t aAddr[2];
#pragma unroll
    for (int mt=0; mt<2; mt++)
        aAddr[mt] = smBase + FSM_FT +
            (uint32_t)(((warpM*32 + mt*16 + lm)*FLD + aco)*2);
    const int bro = (lane & 7) + ((lane >= 16) ? 8 : 0);
    const int bco = (lane & 8) ? 8 : 0;
    uint32_t bOff[4];
#pragma unroll
    for (int p=0; p<4; p++)
        bOff[p] = (uint32_t)(((warpN*64 + p*16 + bro)*FLD + bco)*2);

    const int grow = tid >> 2, gch = tid & 3;
    const uint32_t stLane = smBase + FSM_ST +
        (uint32_t)(((lane & 7) * 72 + ((lane & 8) ? 8 : 0)) * 2);

    const float CEXP  = 0.17677669529663688f * 1.4426950408889634f;
    const float SHIFT = 16.0f * 1.4426950408889634f;

    for (;;) {
        if (tid == 0) s_tile = atomicAdd(&g_ctr_sm, 1u);
        __syncthreads();                 // broadcast + previous-tile smem quiesce
        const unsigned int tile = s_tile;
        if (tile >= SM_TILES) return;
        const int z  = (int)(tile >> 6);
        const int n0 = (int)(tile & 63) * 64;

        {
            const int row = tid >> 2, ch = tid & 3;
            CP_ASYNC16(smBase + FSM_FT + (uint32_t)((row*FLD + ch*8)*2),
                       (const char*)&g_fT[z][n0 + row][ch*8]);
        }
        CP_ASYNC_COMMIT();

        float rsum[4];
#pragma unroll
        for (int i=0;i<4;i++) rsum[i] = 0.f;

        {
            const char* src = (const char*)&g_gT[z][0][0];
#pragma unroll
            for (int i=0;i<4;i++)
                CP_ASYNC16(smBase + FSM_G + (uint32_t)(((grow+i*64)*FLD + gch*8)*2),
                           src + (size_t)(grow + i*64)*64 + gch*16);
            CP_ASYNC_COMMIT();
        }
        for (int t = 0; t < 16; ++t) {
            if (t < 15) {
                const uint32_t dst = smBase + FSM_G + (uint32_t)((t+1)&1)*FSM_GSZ;
                const char* src = (const char*)&g_gT[z][(t+1)*256][0];
#pragma unroll
                for (int i=0;i<4;i++)
                    CP_ASYNC16(dst + (uint32_t)(((grow+i*64)*FLD + gch*8)*2),
                               src + (size_t)(grow + i*64)*64 + gch*16);
                CP_ASYNC_COMMIT();
                CP_ASYNC_WAIT_1();
            } else {
                CP_ASYNC_WAIT_0();
            }
            __syncthreads();

            const uint32_t gb = smBase + FSM_G + (uint32_t)(t&1)*FSM_GSZ;
            float acc[2][8][4];
#pragma unroll
            for (int mt=0;mt<2;mt++)
#pragma unroll
                for (int nt=0;nt<8;nt++)
#pragma unroll
                    for (int c=0;c<4;c++) acc[mt][nt][c] = 0.f;

#pragma unroll
            for (int ks = 0; ks < 2; ++ks) {
                uint32_t a[2][4];
#pragma unroll
                for (int mt=0; mt<2; mt++)
                    LDSM_X4(a[mt][0], a[mt][1], a[mt][2], a[mt][3],
                            aAddr[mt] + ks*32);
                uint32_t bb[4][4];
#pragma unroll
                for (int p=0; p<4; p++)
                    LDSM_X4(bb[p][0], bb[p][1], bb[p][2], bb[p][3],
                            gb + bOff[p] + ks*32);
#pragma unroll
                for (int mt=0; mt<2; mt++)
#pragma unroll
                    for (int nt=0; nt<8; nt++) {
                        const uint32_t b0 = bb[nt>>1][(nt&1)*2];
                        const uint32_t b1 = bb[nt>>1][(nt&1)*2+1];
                        MMA_BF16(acc[mt][nt][0], acc[mt][nt][1],
                                 acc[mt][nt][2], acc[mt][nt][3],
                                 a[mt][0], a[mt][1], a[mt][2], a[mt][3], b0, b1);
                    }
            }

            {
#pragma unroll
                for (int mt=0;mt<2;mt++)
#pragma unroll
                    for (int nt=0;nt<8;nt++){
                        const float p0 = ex2f(fmaf(acc[mt][nt][0], CEXP, -SHIFT));
                        const float p1 = ex2f(fmaf(acc[mt][nt][1], CEXP, -SHIFT));
                        const float p2 = ex2f(fmaf(acc[mt][nt][2], CEXP, -SHIFT));
                        const float p3 = ex2f(fmaf(acc[mt][nt][3], CEXP, -SHIFT));
                        rsum[mt*2+0] += p0 + p1;
                        rsum[mt*2+1] += p2 + p3;
                        __nv_bfloat162 q0 = __float22bfloat162_rn(make_float2(p0, p1));
                        __nv_bfloat162 q1 = __float22bfloat162_rn(make_float2(p2, p3));
                        const uint32_t addr = stLane +
                            (uint32_t)(((warpN*64 + nt*8)*72 + warpM*32 + mt*16) * 2);
                        STSM_X2_TRANS(addr,
                                      reinterpret_cast<uint32_t&>(q0),
                                      reinterpret_cast<uint32_t&>(q1));
                    }
                __syncthreads();
                const int ch = tid & 7;
#pragma unroll
                for (int i=0;i<8;i++){
                    const int ml = (tid>>3) + i*32;
                    const uint4 v = *reinterpret_cast<const uint4*>(
                        sm + FSM_ST + (uint32_t)((ml*72 + ch*8)*2));
                    *reinterpret_cast<uint4*>(&g_Pt[z][t*256 + ml][n0 + ch*8]) = v;
                }
                __syncthreads();
            }
        }

#pragma unroll
        for (int i=0;i<4;i++){
            float v = rsum[i];
            v += __shfl_xor_sync(0xffffffffu, v, 1);
            v += __shfl_xor_sync(0xffffffffu, v, 2);
            rsum[i] = v;
        }
        if (tq == 0) {
#pragma unroll
            for (int i=0;i<4;i++){
                const int r = warpM*32 + (i>>1)*16 + qg + (i&1)*8;
                red[r*4 + warpN] = rsum[i];
            }
        }
        __syncthreads();
        if (warpN == 0 && tq == 0) {
#pragma unroll
            for (int i=0;i<4;i++){
                const int r = warpM*32 + (i>>1)*16 + qg + (i&1)*8;
                const float s = red[r*4+0] + red[r*4+1] + red[r*4+2] + red[r*4+3];
                g_invsum[z][n0 + r] = 1.0f / s;
            }
        }
    }
}

// =====================================================================
// Kernel 3 (dynamic tiles): h projection via HMMA.  1024 tiles.
// =====================================================================
#define PH_LDA   136
#define PH_AST   (64*PH_LDA*2)
#define PH_BST   (128*PH_LDA*2)
#define PH_STG   (PH_AST + PH_BST)
#define PH_SMEM  (2*PH_STG)
#define PH_TILES 1024

__global__ void __launch_bounds__(128, 2) proj_h_mma_kernel(
    const float* __restrict__ h1b, const float* __restrict__ h2b)
{
    extern __shared__ char smh[];
    __shared__ unsigned int s_tile;
    const uint32_t smBase = smem_u32(smh);

    const int tid = threadIdx.x;
    const int wid = tid >> 5, lane = tid & 31;

    const int warpN = wid;
    const int lm  = lane & 15;
    const int aco = (lane >= 16) ? 8 : 0;
    uint32_t aOff[4];
#pragma unroll
    for (int mt=0; mt<4; mt++)
        aOff[mt] = (uint32_t)(((mt*16 + lm)*PH_LDA + aco)*2);
    const int bro = (lane & 7) + ((lane >= 16) ? 8 : 0);
    const int bco = (lane & 8) ? 8 : 0;
    uint32_t bOffA[2];
#pragma unroll
    for (int p=0; p<2; p++)
        bOffA[p] = PH_AST + (uint32_t)(((warpN*32 + p*16 + bro)*PH_LDA + bco)*2);

    const int arow = tid >> 1;
    const int ahalf = (tid & 1) * 128;
    const uint32_t dA = (uint32_t)(arow * (PH_LDA*2) + ahalf);
    const uint32_t dB = PH_AST + (uint32_t)(tid * (PH_LDA*2));

    for (;;) {
        if (tid == 0) s_tile = atomicAdd(&g_ctr_ph, 1u);
        __syncthreads();
        const unsigned int tile = s_tile;
        if (tile >= PH_TILES) return;
        const int z     = (int)(tile >> 7);
        const int oBase = (int)((tile >> 5) & 3) * 64;
        const int nBase = (int)(tile & 31) * 128;
        const int br = z >> 2;
        const float* bias = br ? h2b : h1b;

        const char* gA = (const char*)&g_Wb[br][oBase + arow][0] + ahalf;
        const char* gB = (const char*)&g_Xt[z][nBase + tid][0];

#pragma unroll
        for (int st = 0; st < 2; ++st) {
            const uint32_t slot = smBase + (uint32_t)st * PH_STG;
            const char* sa = gA + (size_t)st * 256;
            const char* sb = gB + (size_t)st * 256;
#pragma unroll
            for (int j=0;j<8;j++)  CP_ASYNC16(slot + dA + j*16, sa + j*16);
#pragma unroll
            for (int j=0;j<16;j++) CP_ASYNC16(slot + dB + j*16, sb + j*16);
            CP_ASYNC_COMMIT();
        }

        float acc[4][4][4];
#pragma unroll
        for (int i=0;i<4;i++)
#pragma unroll
            for (int j=0;j<4;j++)
#pragma unroll
                for (int k=0;k<4;k++) acc[i][j][k] = 0.f;

#pragma unroll
        for (int st = 0; st < 2; ++st) {
            if (st == 0) CP_ASYNC_WAIT_1(); else CP_ASYNC_WAIT_0();
            __syncthreads();
            const uint32_t slot = smBase + (uint32_t)st * PH_STG;
#pragma unroll
            for (int ks = 0; ks < 8; ++ks) {
                uint32_t a[4][4];
#pragma unroll
                for (int mt=0; mt<4; mt++)
                    LDSM_X4(a[mt][0], a[mt][1], a[mt][2], a[mt][3],
                            slot + aOff[mt] + ks*32);
                uint32_t bb[2][4];
#pragma unroll
                for (int p=0; p<2; p++)
                    LDSM_X4(bb[p][0], bb[p][1], bb[p][2], bb[p][3],
                            slot + bOffA[p] + ks*32);
#pragma unroll
                for (int mt=0; mt<4; mt++)
#pragma unroll
                    for (int nt=0; nt<4; nt++) {
                        const uint32_t b0 = bb[nt>>1][(nt&1)*2];
                        const uint32_t b1 = bb[nt>>1][(nt&1)*2+1];
                        MMA_BF16(acc[mt][nt][0], acc[mt][nt][1],
                                 acc[mt][nt][2], acc[mt][nt][3],
                                 a[mt][0], a[mt][1], a[mt][2], a[mt][3], b0, b1);
                    }
            }
        }

        const int g  = lane >> 2;
        const int tq = lane & 3;
#pragma unroll
        for (int mt=0; mt<4; mt++) {
            const int row0 = oBase + mt*16 + g;
            const float bv0 = bias[row0];
            const float bv8 = bias[row0 + 8];
#pragma unroll
            for (int nt=0; nt<4; nt++) {
                const int col = nBase + warpN*32 + nt*8 + tq*2;
                const float2 iv = *reinterpret_cast<const float2*>(&g_invsum[z][col]);
                {
                    const float v0 = (acc[mt][nt][0] + bv0) * iv.x;
                    const float v1 = (acc[mt][nt][1] + bv0) * iv.y;
                    __nv_bfloat162 pk = __float22bfloat162_rn(make_float2(v0, v1));
                    *reinterpret_cast<uint32_t*>(&g_Hb[z][row0][col]) =
                        reinterpret_cast<uint32_t&>(pk);
                }
                {
                    const float v0 = (acc[mt][nt][2] + bv8) * iv.x;
                    const float v1 = (acc[mt][nt][3] + bv8) * iv.y;
                    __nv_bfloat162 pk = __float22bfloat162_rn(make_float2(v0, v1));
                    *reinterpret_cast<uint32_t*>(&g_Hb[z][row0 + 8][col]) =
                        reinterpret_cast<uint32_t&>(pk);
                }
            }
        }
    }
}

// =====================================================================
// Kernel 4 (dynamic tiles): out[z] = gamma*(H'@P') + x.  512 tiles.
// Round-5 pipeline per tile.
// =====================================================================
#define BK      64
#define LDSS    72
#define STGB    (128*LDSS*2)
#define NSTG    3
#define OUT_SMEM (NSTG*2*STGB)
#define OUT_TILES 512

__global__ void __launch_bounds__(256, 2) out_mma_kernel(
    const float* __restrict__ x1, const float* __restrict__ x2,
    const float* __restrict__ gamma1, const float* __restrict__ gamma2,
    float* __restrict__ out)
{
    extern __shared__ char smo[];
    __shared__ unsigned int s_tile;
    const uint32_t smBase = smem_u32(smo);

    const int tid = threadIdx.x;
    const int wid = tid >> 5, lane = tid & 31;

    const int lrow = tid >> 1;
    const int lcol = (tid & 1) * 32;
    const uint32_t ldOff = (uint32_t)((lrow*LDSS + lcol)*2);

    const int warpM = wid >> 2;
    const int warpN = wid & 3;
    const int lm  = lane & 15;
    const int aco = (lane >= 16) ? 8 : 0;
    uint32_t aOff[4];
#pragma unroll
    for (int mt=0; mt<4; mt++)
        aOff[mt] = (uint32_t)(((warpM*64 + mt*16 + lm)*LDSS + aco)*2);
    const int bro = (lane & 7) + ((lane >= 16) ? 8 : 0);
    const int bco = (lane & 8) ? 8 : 0;
    uint32_t bOff[2];
#pragma unroll
    for (int p=0; p<2; p++)
        bOff[p] = (uint32_t)(((warpN*32 + p*16 + bro)*LDSS + bco)*2) + STGB;

    for (;;) {
        if (tid == 0) s_tile = atomicAdd(&g_ctr_out, 1u);
        __syncthreads();
        const unsigned int tile = s_tile;
        if (tile >= OUT_TILES) return;
        const int z     = (int)(tile >> 6);
        const int cBase = (int)((tile >> 5) & 1) * 128;
        const int mBase = (int)(tile & 31) * 128;
        const int br = z >> 2, b = z & 3;
        const float* X = (br ? x2 : x1) + (size_t)b * CH * NPIX;
        const float gamma = (br ? gamma2 : gamma1)[0];

        const char* gAp = (const char*)(&g_Hb[z][cBase + lrow][lcol]);
        const char* gBp = (const char*)(&g_Pt[z][mBase + lrow][lcol]);

        float acc[4][4][4];
#pragma unroll
        for (int i=0;i<4;i++)
#pragma unroll
            for (int j=0;j<4;j++)
#pragma unroll
                for (int k=0;k<4;k++) acc[i][j][k] = 0.f;

#pragma unroll
        for (int st=0; st<2; ++st) {
            const uint32_t slot = smBase + (uint32_t)st * (2*STGB);
            const char* sa = gAp + (size_t)st * (BK*2);
            const char* sb = gBp + (size_t)st * (BK*2);
#pragma unroll
            for (int j=0;j<4;j++) CP_ASYNC16(slot + ldOff + j*16, sa + j*16);
#pragma unroll
            for (int j=0;j<4;j++) CP_ASYNC16(slot + STGB + ldOff + j*16, sb + j*16);
            CP_ASYNC_COMMIT();
        }

        int slotC = 0;
        int slotP = 2;
        for (int it = 0; it < NPIX/BK; ++it) {
            CP_ASYNC_WAIT_1();
            __syncthreads();

            if (it + 2 < NPIX/BK) {
                const uint32_t slot = smBase + (uint32_t)slotP * (2*STGB);
                const char* sa = gAp + (size_t)(it+2) * (BK*2);
                const char* sb = gBp + (size_t)(it+2) * (BK*2);
#pragma unroll
                for (int j=0;j<4;j++) CP_ASYNC16(slot + ldOff + j*16, sa + j*16);
#pragma unroll
                for (int j=0;j<4;j++) CP_ASYNC16(slot + STGB + ldOff + j*16, sb + j*16);
            }
            CP_ASYNC_COMMIT();

            const uint32_t sb = smBase + (uint32_t)slotC * (2*STGB);
#pragma unroll
            for (int ks = 0; ks < 4; ++ks) {
                uint32_t a[4][4];
#pragma unroll
                for (int mt=0; mt<4; mt++)
                    LDSM_X4(a[mt][0], a[mt][1], a[mt][2], a[mt][3],
                            sb + aOff[mt] + ks*32);
                uint32_t bb[2][4];
#pragma unroll
                for (int p=0; p<2; p++)
                    LDSM_X4(bb[p][0], bb[p][1], bb[p][2], bb[p][3],
                            sb + bOff[p] + ks*32);
#pragma unroll
                for (int mt=0; mt<4; mt++)
#pragma unroll
                    for (int nt=0; nt<4; nt++) {
                        const uint32_t b0 = bb[nt>>1][(nt&1)*2];
                        const uint32_t b1 = bb[nt>>1][(nt&1)*2+1];
                        MMA_BF16(acc[mt][nt][0], acc[mt][nt][1],
                                 acc[mt][nt][2], acc[mt][nt][3],
                                 a[mt][0], a[mt][1], a[mt][2], a[mt][3], b0, b1);
                    }
            }

            slotC = (slotC == 2) ? 0 : slotC + 1;
            slotP = (slotP == 2) ? 0 : slotP + 1;
        }

        const int g  = lane >> 2;
        const int tq = lane & 3;
        float* Cz = out + (size_t)z * CH * NPIX;
#pragma unroll
        for (int mt=0; mt<4; mt++) {
            const int row = cBase + warpM*64 + mt*16 + g;
#pragma unroll
            for (int nt=0; nt<4; nt++) {
                const int col = mBase + warpN*32 + nt*8 + tq*2;
                {
                    const float2 xv = *reinterpret_cast<const float2*>(
                        &X[(size_t)row*NPIX + col]);
                    float2 o;
                    o.x = fmaf(gamma, acc[mt][nt][0], xv.x);
                    o.y = fmaf(gamma, acc[mt][nt][1], xv.y);
                    *reinterpret_cast<float2*>(&Cz[(size_t)row*NPIX + col]) = o;
                }
                {
                    const float2 xv = *reinterpret_cast<const float2*>(
                        &X[(size_t)(row+8)*NPIX + col]);
                    float2 o;
                    o.x = fmaf(gamma, acc[mt][nt][2], xv.x);
                    o.y = fmaf(gamma, acc[mt][nt][3], xv.y);
                    *reinterpret_cast<float2*>(&Cz[(size_t)(row+8)*NPIX + col]) = o;
                }
            }
        }
    }
}

// =====================================================================
extern "C" void kernel_launch(void* const* d_in, const int* in_sizes, int n_in,
                              void* d_out, int out_size)
{
    const float* x1     = (const float*)d_in[0];
    const float* x2     = (const float*)d_in[1];
    const float* f_w    = (const float*)d_in[2];
    const float* f_b    = (const float*)d_in[3];
    const float* g_w    = (const float*)d_in[4];
    const float* g_b    = (const float*)d_in[5];
    const float* h1_w   = (const float*)d_in[6];
    const float* h1_b   = (const float*)d_in[7];
    const float* h2_w   = (const float*)d_in[8];
    const float* h2_b   = (const float*)d_in[9];
    const float* gamma1 = (const float*)d_in[10];
    const float* gamma2 = (const float*)d_in[11];
    float* out = (float*)d_out;

    cudaFuncSetAttribute(proj_fg_mma_kernel,
                         cudaFuncAttributeMaxDynamicSharedMemorySize, FG_SMEM);
    cudaFuncSetAttribute(fused_sm_kernel,
                         cudaFuncAttributeMaxDynamicSharedMemorySize, FSM_TOTAL);
    cudaFuncSetAttribute(proj_h_mma_kernel,
                         cudaFuncAttributeMaxDynamicSharedMemorySize, PH_SMEM);
    cudaFuncSetAttribute(out_mma_kernel,
                         cudaFuncAttributeMaxDynamicSharedMemorySize, OUT_SMEM);

    prep_kernel       <<<XT_BLKS + WC_BLKS, 256>>>(
        x1, x2, f_w, g_w, h1_w, h2_w);
    proj_fg_mma_kernel<<<dim3(32, NZ), 128, FG_SMEM>>>(f_b, g_b);
    fused_sm_kernel   <<<dim3(64, NZ), 256, FSM_TOTAL>>>();
    proj_h_mma_kernel <<<dim3(32, 4, NZ), 128, PH_SMEM>>>(h1_b, h2_b);
    out_mma_kernel    <<<dim3(32, 2, NZ), 256, OUT_SMEM>>>(x1, x2, gamma1, gamma2, out);
}